// round 1
// baseline (speedup 1.0000x reference)
#include <cuda_runtime.h>
#include <cstdint>
#include <math.h>

#define EMB 1024
#define SEQ 2048
#define BATCH 2
#define NROWS 4096          // BATCH*SEQ
#define FFDIM 4096
#define NHEADS 16
#define HDIM 64

// -------------------- scratch (no allocation allowed) --------------------
__device__ float g_ln [NROWS * EMB];
__device__ float g_q  [NROWS * EMB];
__device__ float g_k  [NROWS * EMB];
__device__ float g_v  [NROWS * EMB];
__device__ float g_ctx[NROWS * EMB];
__device__ float g_x1 [NROWS * EMB];
__device__ float g_ff [(size_t)NROWS * FFDIM];

// -------------------- helpers --------------------
__device__ __forceinline__ float tf32r(float x) {
    unsigned u;
    asm("cvt.rna.tf32.f32 %0, %1;" : "=r"(u) : "f"(x));
    return __uint_as_float(u);
}

__device__ __forceinline__ void mma8(float* c, const unsigned* a, const unsigned* b) {
    asm volatile(
        "mma.sync.aligned.m16n8k8.row.col.f32.tf32.tf32.f32 "
        "{%0,%1,%2,%3}, {%4,%5,%6,%7}, {%8,%9}, {%0,%1,%2,%3};\n"
        : "+f"(c[0]), "+f"(c[1]), "+f"(c[2]), "+f"(c[3])
        : "r"(a[0]), "r"(a[1]), "r"(a[2]), "r"(a[3]),
          "r"(b[0]), "r"(b[1]));
}

__device__ __forceinline__ float gelu_f(float v) {
    float u = v + 0.044715f * v * v * v;
    return 0.5f * v * (1.0f + tanhf(0.7978845608028654f * u));
}

// -------------------- layernorm --------------------
__global__ void __launch_bounds__(256)
ln_kernel(const float* __restrict__ x, const float* __restrict__ sc,
          const float* __restrict__ sh, float* __restrict__ out)
{
    __shared__ float red[8];
    __shared__ float stats[2];
    const int row = blockIdx.x, tid = threadIdx.x, lane = tid & 31, warp = tid >> 5;
    const float* xr = x + (size_t)row * EMB;
    float4 v = *(const float4*)(xr + tid * 4);

    float s = v.x + v.y + v.z + v.w;
    #pragma unroll
    for (int o = 16; o > 0; o >>= 1) s += __shfl_xor_sync(0xffffffffu, s, o);
    if (lane == 0) red[warp] = s;
    __syncthreads();
    if (tid == 0) {
        float t = 0.f;
        #pragma unroll
        for (int i = 0; i < 8; i++) t += red[i];
        stats[0] = t * (1.0f / EMB);
    }
    __syncthreads();
    const float mean = stats[0];
    float dx = v.x - mean, dy = v.y - mean, dz = v.z - mean, dw = v.w - mean;
    float ss = dx * dx + dy * dy + dz * dz + dw * dw;
    #pragma unroll
    for (int o = 16; o > 0; o >>= 1) ss += __shfl_xor_sync(0xffffffffu, ss, o);
    if (lane == 0) red[warp] = ss;
    __syncthreads();
    if (tid == 0) {
        float t = 0.f;
        #pragma unroll
        for (int i = 0; i < 8; i++) t += red[i];
        stats[1] = rsqrtf(t * (1.0f / EMB) + 1e-5f);
    }
    __syncthreads();
    const float rstd = stats[1];
    float4 scv = *(const float4*)(sc + tid * 4);
    float4 shv = *(const float4*)(sh + tid * 4);
    float4 o4;
    o4.x = scv.x * dx * rstd + shv.x;
    o4.y = scv.y * dy * rstd + shv.y;
    o4.z = scv.z * dz * rstd + shv.z;
    o4.w = scv.w * dw * rstd + shv.w;
    *(float4*)(out + (size_t)row * EMB + tid * 4) = o4;
}

// -------------------- GEMM (tf32 mma.sync, 128x128x32, double-buffered) ----
#define BM 128
#define BN 128
#define BK 32
#define LDA 36    // A tile [BM][LDA]: frag banks (4r+c)%32 distinct -> conflict-free
#define LDB 136   // B tile [BK][LDB]: frag banks (8k+n)%32 distinct -> conflict-free
#define GEMM_SMEM ((2 * BM * LDA + 2 * BK * LDB) * 4)

enum { EP_NONE = 0, EP_BIAS_RES = 1, EP_BIAS_GELU = 2 };

template<int EPI>
__device__ __forceinline__ void store2(float* C, const float* bias, const float* R,
                                       int N, int row, int col, float v0, float v1)
{
    size_t off = (size_t)row * N + col;
    if (EPI == EP_NONE) {
        *(float2*)(C + off) = make_float2(v0, v1);
    } else if (EPI == EP_BIAS_RES) {
        float2 b = *(const float2*)(bias + col);
        float2 r = *(const float2*)(R + off);
        *(float2*)(C + off) = make_float2(v0 + b.x + r.x, v1 + b.y + r.y);
    } else {  // EP_BIAS_GELU
        float2 b = *(const float2*)(bias + col);
        *(float2*)(C + off) = make_float2(gelu_f(v0 + b.x), gelu_f(v1 + b.y));
    }
}

template<int EPI>
__global__ void __launch_bounds__(256)
gemm_kernel(const float* __restrict__ A, const float* __restrict__ B,
            const float* __restrict__ bias, const float* __restrict__ R,
            float* __restrict__ C, int M, int N, int K)
{
    extern __shared__ float sm[];
    float* As = sm;                         // 2 buffers of [BM][LDA]
    float* Bs = sm + 2 * BM * LDA;          // 2 buffers of [BK][LDB]

    const int tid = threadIdx.x, lane = tid & 31, warp = tid >> 5;
    const int bm = blockIdx.y * BM, bn = blockIdx.x * BN;
    const int wm = (warp & 1) * 64, wn = (warp >> 1) * 32;
    const int arow = tid >> 3, acol = (tid & 7) * 4;
    const int brow = tid >> 5, bcol = (tid & 31) * 4;
    const int g = lane >> 2, t = lane & 3;

    float c[4][4][4];
    #pragma unroll
    for (int mt = 0; mt < 4; mt++)
        #pragma unroll
        for (int nt = 0; nt < 4; nt++)
            #pragma unroll
            for (int e = 0; e < 4; e++) c[mt][nt][e] = 0.f;

    const int NK = K / BK;

    // tile 0 -> smem buffer 0 (convert to tf32 on store)
    #pragma unroll
    for (int i = 0; i < 4; i++) {
        int r = arow + i * 32;
        float4 tv = *(const float4*)(A + (size_t)(bm + r) * K + acol);
        float* d = As + r * LDA + acol;
        d[0] = tf32r(tv.x); d[1] = tf32r(tv.y); d[2] = tf32r(tv.z); d[3] = tf32r(tv.w);
    }
    #pragma unroll
    for (int i = 0; i < 4; i++) {
        int r = brow + i * 8;
        float4 tv = *(const float4*)(B + (size_t)r * N + bn + bcol);
        float* d = Bs + r * LDB + bcol;
        d[0] = tf32r(tv.x); d[1] = tf32r(tv.y); d[2] = tf32r(tv.z); d[3] = tf32r(tv.w);
    }
    __syncthreads();

    for (int kt = 0; kt < NK; kt++) {
        const float* Ac = As + (kt & 1) * (BM * LDA);
        const float* Bc = Bs + (kt & 1) * (BK * LDB);

        float4 pa[4], pb[4];
        const bool pre = (kt + 1 < NK);
        if (pre) {
            const int k0 = (kt + 1) * BK;
            #pragma unroll
            for (int i = 0; i < 4; i++)
                pa[i] = *(const float4*)(A + (size_t)(bm + arow + i * 32) * K + k0 + acol);
            #pragma unroll
            for (int i = 0; i < 4; i++)
                pb[i] = *(const float4*)(B + (size_t)(k0 + brow + i * 8) * N + bn + bcol);
        }

        #pragma unroll
        for (int ks = 0; ks < 4; ks++) {
            const int kb = ks * 8;
            unsigned a[4][4], b[4][2];
            #pragma unroll
            for (int mt = 0; mt < 4; mt++) {
                const float* p = Ac + (wm + mt * 16 + g) * LDA + kb + t;
                a[mt][0] = __float_as_uint(p[0]);
                a[mt][1] = __float_as_uint(p[8 * LDA]);
                a[mt][2] = __float_as_uint(p[4]);
                a[mt][3] = __float_as_uint(p[8 * LDA + 4]);
            }
            #pragma unroll
            for (int nt = 0; nt < 4; nt++) {
                const float* p = Bc + (kb + t) * LDB + wn + nt * 8 + g;
                b[nt][0] = __float_as_uint(p[0]);
                b[nt][1] = __float_as_uint(p[4 * LDB]);
            }
            #pragma unroll
            for (int mt = 0; mt < 4; mt++)
                #pragma unroll
                for (int nt = 0; nt < 4; nt++)
                    mma8(c[mt][nt], a[mt], b[nt]);
        }

        if (pre) {
            float* Ad = As + ((kt + 1) & 1) * (BM * LDA);
            float* Bd = Bs + ((kt + 1) & 1) * (BK * LDB);
            #pragma unroll
            for (int i = 0; i < 4; i++) {
                float* d = Ad + (arow + i * 32) * LDA + acol;
                d[0] = tf32r(pa[i].x); d[1] = tf32r(pa[i].y);
                d[2] = tf32r(pa[i].z); d[3] = tf32r(pa[i].w);
            }
            #pragma unroll
            for (int i = 0; i < 4; i++) {
                float* d = Bd + (brow + i * 8) * LDB + bcol;
                d[0] = tf32r(pb[i].x); d[1] = tf32r(pb[i].y);
                d[2] = tf32r(pb[i].z); d[3] = tf32r(pb[i].w);
            }
            __syncthreads();
        }
    }

    // epilogue
    #pragma unroll
    for (int mt = 0; mt < 4; mt++) {
        #pragma unroll
        for (int nt = 0; nt < 4; nt++) {
            int row = bm + wm + mt * 16 + g;
            int col = bn + wn + nt * 8 + t * 2;
            store2<EPI>(C, bias, R, N, row,     col, c[mt][nt][0], c[mt][nt][1]);
            store2<EPI>(C, bias, R, N, row + 8, col, c[mt][nt][2], c[mt][nt][3]);
        }
    }
}

// -------------------- causal flash attention (Br=Bc=64, d=64) --------------
#define ALD 68
#define ATT_SMEM ((3 * 64 * ALD + 4 * 16 * ALD) * 4)

__global__ void __launch_bounds__(128)
attn_kernel(const float* __restrict__ Q, const float* __restrict__ Kg,
            const float* __restrict__ Vg, float* __restrict__ O)
{
    extern __shared__ float sm[];
    float* Qs = sm;
    float* Ks = sm + 64 * ALD;
    float* Vs = sm + 2 * 64 * ALD;

    const int tid = threadIdx.x, lane = tid & 31, warp = tid >> 5;
    const int g = lane >> 2, t = lane & 3;
    float* Ps = sm + 3 * 64 * ALD + warp * 16 * ALD;

    const int qt = blockIdx.x;            // query tile 0..31
    const int bh = blockIdx.y;            // b*16+h
    const int b = bh >> 4, h = bh & 15;
    const size_t base = (size_t)b * SEQ * EMB + (size_t)h * HDIM;

    // load Q tile (rows qt*64..qt*64+63, d=0..63), tf32-rounded
    #pragma unroll
    for (int i = 0; i < 8; i++) {
        int idx = tid + i * 128, r = idx >> 4, c = (idx & 15) * 4;
        float4 tv = *(const float4*)(Q + base + (size_t)(qt * 64 + r) * EMB + c);
        float* d = Qs + r * ALD + c;
        d[0] = tf32r(tv.x); d[1] = tf32r(tv.y); d[2] = tf32r(tv.z); d[3] = tf32r(tv.w);
    }

    float m0 = -1e30f, m1 = -1e30f, l0 = 0.f, l1 = 0.f;
    float o[8][4];
    #pragma unroll
    for (int dt = 0; dt < 8; dt++)
        #pragma unroll
        for (int e = 0; e < 4; e++) o[dt][e] = 0.f;

    const int r0g = qt * 64 + warp * 16 + g;   // global query row for c0/c1 (c2/c3 -> +8)

    for (int j = 0; j <= qt; j++) {
        __syncthreads();
        // load K,V tile j
        #pragma unroll
        for (int i = 0; i < 8; i++) {
            int idx = tid + i * 128, r = idx >> 4, c = (idx & 15) * 4;
            size_t go = base + (size_t)(j * 64 + r) * EMB + c;
            float4 kv = *(const float4*)(Kg + go);
            float4 vv = *(const float4*)(Vg + go);
            float* dk = Ks + r * ALD + c;
            dk[0] = tf32r(kv.x); dk[1] = tf32r(kv.y); dk[2] = tf32r(kv.z); dk[3] = tf32r(kv.w);
            float* dv = Vs + r * ALD + c;
            dv[0] = tf32r(vv.x); dv[1] = tf32r(vv.y); dv[2] = tf32r(vv.z); dv[3] = tf32r(vv.w);
        }
        __syncthreads();

        // S = Q K^T  (per warp: 16 x 64)
        float s[8][4];
        #pragma unroll
        for (int nt = 0; nt < 8; nt++)
            #pragma unroll
            for (int e = 0; e < 4; e++) s[nt][e] = 0.f;

        #pragma unroll
        for (int ks = 0; ks < 8; ks++) {
            unsigned a[4];
            const float* ap = Qs + (warp * 16 + g) * ALD + ks * 8 + t;
            a[0] = __float_as_uint(ap[0]);
            a[1] = __float_as_uint(ap[8 * ALD]);
            a[2] = __float_as_uint(ap[4]);
            a[3] = __float_as_uint(ap[8 * ALD + 4]);
            #pragma unroll
            for (int nt = 0; nt < 8; nt++) {
                unsigned bb[2];
                const float* bp = Ks + (nt * 8 + g) * ALD + ks * 8 + t;
                bb[0] = __float_as_uint(bp[0]);
                bb[1] = __float_as_uint(bp[4]);
                mma8(s[nt], a, bb);
            }
        }

        // scale (ref scales after masking; equivalent) + causal mask on diagonal
        #pragma unroll
        for (int nt = 0; nt < 8; nt++)
            #pragma unroll
            for (int e = 0; e < 4; e++) s[nt][e] *= 0.125f;
        if (j == qt) {
            #pragma unroll
            for (int nt = 0; nt < 8; nt++) {
                int cb = j * 64 + nt * 8 + t * 2;
                if (cb     > r0g)     s[nt][0] = -1e30f;
                if (cb + 1 > r0g)     s[nt][1] = -1e30f;
                if (cb     > r0g + 8) s[nt][2] = -1e30f;
                if (cb + 1 > r0g + 8) s[nt][3] = -1e30f;
            }
        }

        // online softmax (two rows per thread)
        float t0 = -1e30f, t1 = -1e30f;
        #pragma unroll
        for (int nt = 0; nt < 8; nt++) {
            t0 = fmaxf(t0, fmaxf(s[nt][0], s[nt][1]));
            t1 = fmaxf(t1, fmaxf(s[nt][2], s[nt][3]));
        }
        t0 = fmaxf(t0, __shfl_xor_sync(0xffffffffu, t0, 1));
        t0 = fmaxf(t0, __shfl_xor_sync(0xffffffffu, t0, 2));
        t1 = fmaxf(t1, __shfl_xor_sync(0xffffffffu, t1, 1));
        t1 = fmaxf(t1, __shfl_xor_sync(0xffffffffu, t1, 2));
        float mn0 = fmaxf(m0, t0), mn1 = fmaxf(m1, t1);
        float al0 = __expf(m0 - mn0), al1 = __expf(m1 - mn1);
        float su0 = 0.f, su1 = 0.f;
        #pragma unroll
        for (int nt = 0; nt < 8; nt++) {
            s[nt][0] = __expf(s[nt][0] - mn0); su0 += s[nt][0];
            s[nt][1] = __expf(s[nt][1] - mn0); su0 += s[nt][1];
            s[nt][2] = __expf(s[nt][2] - mn1); su1 += s[nt][2];
            s[nt][3] = __expf(s[nt][3] - mn1); su1 += s[nt][3];
        }
        su0 += __shfl_xor_sync(0xffffffffu, su0, 1);
        su0 += __shfl_xor_sync(0xffffffffu, su0, 2);
        su1 += __shfl_xor_sync(0xffffffffu, su1, 1);
        su1 += __shfl_xor_sync(0xffffffffu, su1, 2);
        l0 = l0 * al0 + su0; l1 = l1 * al1 + su1;
        m0 = mn0; m1 = mn1;
        #pragma unroll
        for (int dt = 0; dt < 8; dt++) {
            o[dt][0] *= al0; o[dt][1] *= al0;
            o[dt][2] *= al1; o[dt][3] *= al1;
        }

        // P: C-layout -> per-warp smem -> A-layout
        #pragma unroll
        for (int nt = 0; nt < 8; nt++) {
            float* pp = Ps + g * ALD + nt * 8 + t * 2;
            pp[0] = tf32r(s[nt][0]); pp[1] = tf32r(s[nt][1]);
            pp[8 * ALD] = tf32r(s[nt][2]); pp[8 * ALD + 1] = tf32r(s[nt][3]);
        }
        __syncwarp();

        // O += P @ V
        #pragma unroll
        for (int ks = 0; ks < 8; ks++) {
            unsigned a[4];
            const float* ap = Ps + g * ALD + ks * 8 + t;
            a[0] = __float_as_uint(ap[0]);
            a[1] = __float_as_uint(ap[8 * ALD]);
            a[2] = __float_as_uint(ap[4]);
            a[3] = __float_as_uint(ap[8 * ALD + 4]);
            #pragma unroll
            for (int dt = 0; dt < 8; dt++) {
                unsigned bb[2];
                const float* bp = Vs + (ks * 8 + t) * ALD + dt * 8 + g;
                bb[0] = __float_as_uint(bp[0]);
                bb[1] = __float_as_uint(bp[4 * ALD]);
                mma8(o[dt], a, bb);
            }
        }
        __syncwarp();
    }

    const float i0 = 1.0f / l0, i1 = 1.0f / l1;
    #pragma unroll
    for (int dt = 0; dt < 8; dt++) {
        int col = dt * 8 + t * 2;
        size_t off0 = base + (size_t)r0g * EMB + col;
        size_t off1 = base + (size_t)(r0g + 8) * EMB + col;
        *(float2*)(O + off0) = make_float2(o[dt][0] * i0, o[dt][1] * i0);
        *(float2*)(O + off1) = make_float2(o[dt][2] * i1, o[dt][3] * i1);
    }
}

// -------------------- launch --------------------
extern "C" void kernel_launch(void* const* d_in, const int* in_sizes, int n_in,
                              void* d_out, int out_size)
{
    const float* x     = (const float*)d_in[0];
    const float* w_q   = (const float*)d_in[1];
    const float* w_k   = (const float*)d_in[2];
    const float* w_v   = (const float*)d_in[3];
    const float* w_o   = (const float*)d_in[4];
    const float* b_o   = (const float*)d_in[5];
    const float* ln1s  = (const float*)d_in[6];
    const float* ln1b  = (const float*)d_in[7];
    const float* ln2s  = (const float*)d_in[8];
    const float* ln2b  = (const float*)d_in[9];
    const float* w_ff1 = (const float*)d_in[10];
    const float* b_ff1 = (const float*)d_in[11];
    const float* w_ff2 = (const float*)d_in[12];
    const float* b_ff2 = (const float*)d_in[13];
    float* out = (float*)d_out;

    float *ln, *q, *k, *v, *ctx, *x1, *ff;
    cudaGetSymbolAddress((void**)&ln,  g_ln);
    cudaGetSymbolAddress((void**)&q,   g_q);
    cudaGetSymbolAddress((void**)&k,   g_k);
    cudaGetSymbolAddress((void**)&v,   g_v);
    cudaGetSymbolAddress((void**)&ctx, g_ctx);
    cudaGetSymbolAddress((void**)&x1,  g_x1);
    cudaGetSymbolAddress((void**)&ff,  g_ff);

    cudaFuncSetAttribute((const void*)gemm_kernel<EP_NONE>,
                         cudaFuncAttributeMaxDynamicSharedMemorySize, GEMM_SMEM);
    cudaFuncSetAttribute((const void*)gemm_kernel<EP_BIAS_RES>,
                         cudaFuncAttributeMaxDynamicSharedMemorySize, GEMM_SMEM);
    cudaFuncSetAttribute((const void*)gemm_kernel<EP_BIAS_GELU>,
                         cudaFuncAttributeMaxDynamicSharedMemorySize, GEMM_SMEM);
    cudaFuncSetAttribute((const void*)attn_kernel,
                         cudaFuncAttributeMaxDynamicSharedMemorySize, ATT_SMEM);

    const dim3 gEmb(EMB / BN, NROWS / BM);     // (8, 32)
    const dim3 gFf(FFDIM / BN, NROWS / BM);    // (32, 32)

    // h = LN1(x)
    ln_kernel<<<NROWS, 256>>>(x, ln1s, ln1b, ln);
    // q,k,v = h @ W
    gemm_kernel<EP_NONE><<<gEmb, 256, GEMM_SMEM>>>(ln, w_q, nullptr, nullptr, q, NROWS, EMB, EMB);
    gemm_kernel<EP_NONE><<<gEmb, 256, GEMM_SMEM>>>(ln, w_k, nullptr, nullptr, k, NROWS, EMB, EMB);
    gemm_kernel<EP_NONE><<<gEmb, 256, GEMM_SMEM>>>(ln, w_v, nullptr, nullptr, v, NROWS, EMB, EMB);
    // ctx = causal attention
    attn_kernel<<<dim3(SEQ / 64, BATCH * NHEADS), 128, ATT_SMEM>>>(q, k, v, ctx);
    // x1 = x + ctx @ w_o + b_o
    gemm_kernel<EP_BIAS_RES><<<gEmb, 256, GEMM_SMEM>>>(ctx, w_o, b_o, x, x1, NROWS, EMB, EMB);
    // h = LN2(x1)
    ln_kernel<<<NROWS, 256>>>(x1, ln2s, ln2b, ln);
    // ff = gelu(h @ w_ff1 + b_ff1)
    gemm_kernel<EP_BIAS_GELU><<<gFf, 256, GEMM_SMEM>>>(ln, w_ff1, b_ff1, nullptr, ff, NROWS, FFDIM, EMB);
    // out = x1 + ff @ w_ff2 + b_ff2
    gemm_kernel<EP_BIAS_RES><<<gEmb, 256, GEMM_SMEM>>>(ff, w_ff2, b_ff2, x1, out, NROWS, EMB, FFDIM);
}

// round 4
// speedup vs baseline: 1.1846x; 1.1846x over previous
#include <cuda_runtime.h>
#include <cstdint>
#include <math.h>

#define EMB 1024
#define SEQ 2048
#define BATCH 2
#define NROWS 4096          // BATCH*SEQ
#define FFDIM 4096
#define NHEADS 16
#define HDIM 64

// -------------------- scratch (no allocation allowed) --------------------
__device__ float g_ln  [NROWS * EMB];
__device__ float g_qkv [(size_t)NROWS * 3 * EMB];
__device__ float g_ctx [NROWS * EMB];
__device__ float g_x1  [NROWS * EMB];
__device__ float g_ff  [(size_t)NROWS * FFDIM];
__device__ float g_wqkv[(size_t)EMB * 3 * EMB];   // [1024][3072] tf32-rounded
__device__ float g_wo  [(size_t)EMB * EMB];       // [1024][1024]
__device__ float g_wf1 [(size_t)EMB * FFDIM];     // [1024][4096]
__device__ float g_wf2 [(size_t)FFDIM * EMB];     // [4096][1024]

// -------------------- helpers --------------------
__device__ __forceinline__ float tf32r(float x) {
    unsigned u;
    asm("cvt.rna.tf32.f32 %0, %1;" : "=r"(u) : "f"(x));
    return __uint_as_float(u);
}

__device__ __forceinline__ float gelu_f(float v) {
    float u = v + 0.044715f * v * v * v;
    return 0.5f * v * (1.0f + tanhf(0.7978845608028654f * u));
}

__device__ __forceinline__ uint32_t smem_u32(const void* p) {
    uint32_t a;
    asm("{ .reg .u64 t; cvta.to.shared.u64 t, %1; cvt.u32.u64 %0, t; }" : "=r"(a) : "l"(p));
    return a;
}

__device__ __forceinline__ void mma8(float* c, const unsigned* a, const unsigned* b) {
    asm volatile(
        "mma.sync.aligned.m16n8k8.row.col.f32.tf32.tf32.f32 "
        "{%0,%1,%2,%3}, {%4,%5,%6,%7}, {%8,%9}, {%0,%1,%2,%3};\n"
        : "+f"(c[0]), "+f"(c[1]), "+f"(c[2]), "+f"(c[3])
        : "r"(a[0]), "r"(a[1]), "r"(a[2]), "r"(a[3]),
          "r"(b[0]), "r"(b[1]));
}

// ---- cp.async ----
__device__ __forceinline__ void cpa16(uint32_t dst, const float* src) {
    asm volatile("cp.async.cg.shared.global [%0], [%1], 16;" :: "r"(dst), "l"(src));
}
#define CPA_COMMIT() asm volatile("cp.async.commit_group;" ::: "memory")
template<int N> __device__ __forceinline__ void cpa_wait() {
    asm volatile("cp.async.wait_group %0;" :: "n"(N) : "memory");
}

// -------------------- weight rounding [rows][cols] -> strided dest ---------
__global__ void __launch_bounds__(256)
round_strided(const float* __restrict__ in, float* __restrict__ out,
              int cols, int ldo, int total4)
{
    int idx = blockIdx.x * 256 + threadIdx.x;
    if (idx >= total4) return;
    int c4 = cols >> 2;
    int r = idx / c4, c = (idx - r * c4) * 4;
    float4 v = *(const float4*)(in + (size_t)r * cols + c);
    v.x = tf32r(v.x); v.y = tf32r(v.y); v.z = tf32r(v.z); v.w = tf32r(v.w);
    *(float4*)(out + (size_t)r * ldo + c) = v;
}

// -------------------- layernorm (tf32-rounded output) ----------------------
__global__ void __launch_bounds__(256)
ln_kernel(const float* __restrict__ x, const float* __restrict__ sc,
          const float* __restrict__ sh, float* __restrict__ out)
{
    __shared__ float red[8];
    __shared__ float stats[2];
    const int row = blockIdx.x, tid = threadIdx.x, lane = tid & 31, warp = tid >> 5;
    const float* xr = x + (size_t)row * EMB;
    float4 v = *(const float4*)(xr + tid * 4);

    float s = v.x + v.y + v.z + v.w;
    #pragma unroll
    for (int o = 16; o > 0; o >>= 1) s += __shfl_xor_sync(0xffffffffu, s, o);
    if (lane == 0) red[warp] = s;
    __syncthreads();
    if (tid == 0) {
        float t = 0.f;
        #pragma unroll
        for (int i = 0; i < 8; i++) t += red[i];
        stats[0] = t * (1.0f / EMB);
    }
    __syncthreads();
    const float mean = stats[0];
    float dx = v.x - mean, dy = v.y - mean, dz = v.z - mean, dw = v.w - mean;
    float ss = dx * dx + dy * dy + dz * dz + dw * dw;
    #pragma unroll
    for (int o = 16; o > 0; o >>= 1) ss += __shfl_xor_sync(0xffffffffu, ss, o);
    if (lane == 0) red[warp] = ss;
    __syncthreads();
    if (tid == 0) {
        float t = 0.f;
        #pragma unroll
        for (int i = 0; i < 8; i++) t += red[i];
        stats[1] = rsqrtf(t * (1.0f / EMB) + 1e-5f);
    }
    __syncthreads();
    const float rstd = stats[1];
    float4 scv = *(const float4*)(sc + tid * 4);
    float4 shv = *(const float4*)(sh + tid * 4);
    float4 o4;
    o4.x = tf32r(scv.x * dx * rstd + shv.x);
    o4.y = tf32r(scv.y * dy * rstd + shv.y);
    o4.z = tf32r(scv.z * dz * rstd + shv.z);
    o4.w = tf32r(scv.w * dw * rstd + shv.w);
    *(float4*)(out + (size_t)row * EMB + tid * 4) = o4;
}

// -------------------- GEMM (tf32 mma.sync, 128x128x32, cp.async 3-stage) ---
#define BM 128
#define BN 128
#define BK 32
#define LDA 36    // A tile [BM][LDA]
#define LDB 136   // B tile [BK][LDB]
#define STGF (BM * LDA + BK * LDB)              // floats per stage = 8960
#define GEMM_SMEM (3 * STGF * 4)                // 107520 bytes

enum { EP_NONE = 0, EP_BIAS_RES = 1, EP_BIAS_GELU = 2 };

template<int EPI>
__device__ __forceinline__ void store2(float* C, const float* bias, const float* R,
                                       int N, int row, int col, float v0, float v1)
{
    size_t off = (size_t)row * N + col;
    if (EPI == EP_NONE) {
        *(float2*)(C + off) = make_float2(v0, v1);
    } else if (EPI == EP_BIAS_RES) {
        float2 b = *(const float2*)(bias + col);
        float2 r = *(const float2*)(R + off);
        *(float2*)(C + off) = make_float2(v0 + b.x + r.x, v1 + b.y + r.y);
    } else {  // EP_BIAS_GELU (tf32-rounded: feeds next GEMM's A)
        float2 b = *(const float2*)(bias + col);
        *(float2*)(C + off) = make_float2(tf32r(gelu_f(v0 + b.x)), tf32r(gelu_f(v1 + b.y)));
    }
}

__device__ __forceinline__ void fill_stage(float* stage,
                                           const float* __restrict__ A,
                                           const float* __restrict__ B,
                                           int bm, int bn, int N, int K, int kc, int tid)
{
    const int arow = tid >> 3, acol = (tid & 7) * 4;
    const float* asrc = A + (size_t)(bm + arow) * K + kc * BK + acol;
    uint32_t adst = smem_u32(stage + arow * LDA + acol);
    #pragma unroll
    for (int i = 0; i < 4; i++)
        cpa16(adst + i * (32 * LDA * 4), asrc + (size_t)i * 32 * K);

    const int brow = tid >> 5, bcol = (tid & 31) * 4;
    const float* bsrc = B + (size_t)(kc * BK + brow) * N + bn + bcol;
    uint32_t bdst = smem_u32(stage + BM * LDA + brow * LDB + bcol);
    #pragma unroll
    for (int i = 0; i < 4; i++)
        cpa16(bdst + i * (8 * LDB * 4), bsrc + (size_t)i * 8 * N);
}

template<int EPI>
__global__ void __launch_bounds__(256, 2)
gemm_kernel(const float* __restrict__ A, const float* __restrict__ B,
            const float* __restrict__ bias, const float* __restrict__ R,
            float* __restrict__ C, int M, int N, int K)
{
    extern __shared__ float sm[];

    const int tid = threadIdx.x, lane = tid & 31, warp = tid >> 5;
    const int bm = blockIdx.y * BM, bn = blockIdx.x * BN;
    const int wm = (warp & 1) * 64, wn = (warp >> 1) * 32;
    const int g = lane >> 2, t = lane & 3;
    const int NK = K / BK;

    float c[4][4][4];
    #pragma unroll
    for (int mt = 0; mt < 4; mt++)
        #pragma unroll
        for (int nt = 0; nt < 4; nt++)
            #pragma unroll
            for (int e = 0; e < 4; e++) c[mt][nt][e] = 0.f;

    // prologue: stages 0,1
    fill_stage(sm,        A, B, bm, bn, N, K, 0, tid);
    CPA_COMMIT();
    fill_stage(sm + STGF, A, B, bm, bn, N, K, 1, tid);
    CPA_COMMIT();

    int stg = 0;
    for (int kt = 0; kt < NK; kt++) {
        if (kt == NK - 1) cpa_wait<0>(); else cpa_wait<1>();
        __syncthreads();

        if (kt + 2 < NK) {
            int fs = kt + 2 - ((kt + 2) / 3) * 3;
            fill_stage(sm + fs * STGF, A, B, bm, bn, N, K, kt + 2, tid);
            CPA_COMMIT();
        }

        const float* Ac = sm + stg * STGF;
        const float* Bc = Ac + BM * LDA;

        #pragma unroll
        for (int ks = 0; ks < 4; ks++) {
            const int kb = ks * 8;
            unsigned a[4][4], b[4][2];
            #pragma unroll
            for (int mt = 0; mt < 4; mt++) {
                const float* p = Ac + (wm + mt * 16 + g) * LDA + kb + t;
                a[mt][0] = __float_as_uint(p[0]);
                a[mt][1] = __float_as_uint(p[8 * LDA]);
                a[mt][2] = __float_as_uint(p[4]);
                a[mt][3] = __float_as_uint(p[8 * LDA + 4]);
            }
            #pragma unroll
            for (int nt = 0; nt < 4; nt++) {
                const float* p = Bc + (kb + t) * LDB + wn + nt * 8 + g;
                b[nt][0] = __float_as_uint(p[0]);
                b[nt][1] = __float_as_uint(p[4 * LDB]);
            }
            #pragma unroll
            for (int mt = 0; mt < 4; mt++)
                #pragma unroll
                for (int nt = 0; nt < 4; nt++)
                    mma8(c[mt][nt], a[mt], b[nt]);
        }

        stg++; if (stg == 3) stg = 0;
    }

    // epilogue
    #pragma unroll
    for (int mt = 0; mt < 4; mt++) {
        #pragma unroll
        for (int nt = 0; nt < 4; nt++) {
            int row = bm + wm + mt * 16 + g;
            int col = bn + wn + nt * 8 + t * 2;
            store2<EPI>(C, bias, R, N, row,     col, c[mt][nt][0], c[mt][nt][1]);
            store2<EPI>(C, bias, R, N, row + 8, col, c[mt][nt][2], c[mt][nt][3]);
        }
    }
}

// -------------------- causal flash attention (Br=Bc=64, d=64) --------------
#define ALD 68
#define ATT_SMEM ((3 * 64 * ALD + 4 * 16 * ALD) * 4)

__global__ void __launch_bounds__(128)
attn_kernel(const float* __restrict__ Q, const float* __restrict__ Kg,
            const float* __restrict__ Vg, float* __restrict__ O, int ldq)
{
    extern __shared__ float sm[];
    float* Qs = sm;
    float* Ks = sm + 64 * ALD;
    float* Vs = sm + 2 * 64 * ALD;

    const int tid = threadIdx.x, lane = tid & 31, warp = tid >> 5;
    const int g = lane >> 2, t = lane & 3;
    float* Ps = sm + 3 * 64 * ALD + warp * 16 * ALD;

    const int qt = blockIdx.x;
    const int bh = blockIdx.y;
    const int b = bh >> 4, h = bh & 15;
    const size_t base  = (size_t)b * SEQ * ldq + (size_t)h * HDIM;
    const size_t obase = (size_t)b * SEQ * EMB + (size_t)h * HDIM;

    #pragma unroll
    for (int i = 0; i < 8; i++) {
        int idx = tid + i * 128, r = idx >> 4, c = (idx & 15) * 4;
        float4 tv = *(const float4*)(Q + base + (size_t)(qt * 64 + r) * ldq + c);
        float* d = Qs + r * ALD + c;
        d[0] = tf32r(tv.x); d[1] = tf32r(tv.y); d[2] = tf32r(tv.z); d[3] = tf32r(tv.w);
    }

    float m0 = -1e30f, m1 = -1e30f, l0 = 0.f, l1 = 0.f;
    float o[8][4];
    #pragma unroll
    for (int dt = 0; dt < 8; dt++)
        #pragma unroll
        for (int e = 0; e < 4; e++) o[dt][e] = 0.f;

    const int r0g = qt * 64 + warp * 16 + g;

    for (int j = 0; j <= qt; j++) {
        __syncthreads();
        #pragma unroll
        for (int i = 0; i < 8; i++) {
            int idx = tid + i * 128, r = idx >> 4, c = (idx & 15) * 4;
            size_t go = base + (size_t)(j * 64 + r) * ldq + c;
            float4 kv = *(const float4*)(Kg + go);
            float4 vv = *(const float4*)(Vg + go);
            float* dk = Ks + r * ALD + c;
            dk[0] = tf32r(kv.x); dk[1] = tf32r(kv.y); dk[2] = tf32r(kv.z); dk[3] = tf32r(kv.w);
            float* dv = Vs + r * ALD + c;
            dv[0] = tf32r(vv.x); dv[1] = tf32r(vv.y); dv[2] = tf32r(vv.z); dv[3] = tf32r(vv.w);
        }
        __syncthreads();

        float s[8][4];
        #pragma unroll
        for (int nt = 0; nt < 8; nt++)
            #pragma unroll
            for (int e = 0; e < 4; e++) s[nt][e] = 0.f;

        #pragma unroll
        for (int ks = 0; ks < 8; ks++) {
            unsigned a[4];
            const float* ap = Qs + (warp * 16 + g) * ALD + ks * 8 + t;
            a[0] = __float_as_uint(ap[0]);
            a[1] = __float_as_uint(ap[8 * ALD]);
            a[2] = __float_as_uint(ap[4]);
            a[3] = __float_as_uint(ap[8 * ALD + 4]);
            #pragma unroll
            for (int nt = 0; nt < 8; nt++) {
                unsigned bb[2];
                const float* bp = Ks + (nt * 8 + g) * ALD + ks * 8 + t;
                bb[0] = __float_as_uint(bp[0]);
                bb[1] = __float_as_uint(bp[4]);
                mma8(s[nt], a, bb);
            }
        }

        #pragma unroll
        for (int nt = 0; nt < 8; nt++)
            #pragma unroll
            for (int e = 0; e < 4; e++) s[nt][e] *= 0.125f;
        if (j == qt) {
            #pragma unroll
            for (int nt = 0; nt < 8; nt++) {
                int cb = j * 64 + nt * 8 + t * 2;
                if (cb     > r0g)     s[nt][0] = -1e30f;
                if (cb + 1 > r0g)     s[nt][1] = -1e30f;
                if (cb     > r0g + 8) s[nt][2] = -1e30f;
                if (cb + 1 > r0g + 8) s[nt][3] = -1e30f;
            }
        }

        float t0 = -1e30f, t1 = -1e30f;
        #pragma unroll
        for (int nt = 0; nt < 8; nt++) {
            t0 = fmaxf(t0, fmaxf(s[nt][0], s[nt][1]));
            t1 = fmaxf(t1, fmaxf(s[nt][2], s[nt][3]));
        }
        t0 = fmaxf(t0, __shfl_xor_sync(0xffffffffu, t0, 1));
        t0 = fmaxf(t0, __shfl_xor_sync(0xffffffffu, t0, 2));
        t1 = fmaxf(t1, __shfl_xor_sync(0xffffffffu, t1, 1));
        t1 = fmaxf(t1, __shfl_xor_sync(0xffffffffu, t1, 2));
        float mn0 = fmaxf(m0, t0), mn1 = fmaxf(m1, t1);
        float al0 = __expf(m0 - mn0), al1 = __expf(m1 - mn1);
        float su0 = 0.f, su1 = 0.f;
        #pragma unroll
        for (int nt = 0; nt < 8; nt++) {
            s[nt][0] = __expf(s[nt][0] - mn0); su0 += s[nt][0];
            s[nt][1] = __expf(s[nt][1] - mn0); su0 += s[nt][1];
            s[nt][2] = __expf(s[nt][2] - mn1); su1 += s[nt][2];
            s[nt][3] = __expf(s[nt][3] - mn1); su1 += s[nt][3];
        }
        su0 += __shfl_xor_sync(0xffffffffu, su0, 1);
        su0 += __shfl_xor_sync(0xffffffffu, su0, 2);
        su1 += __shfl_xor_sync(0xffffffffu, su1, 1);
        su1 += __shfl_xor_sync(0xffffffffu, su1, 2);
        l0 = l0 * al0 + su0; l1 = l1 * al1 + su1;
        m0 = mn0; m1 = mn1;
        #pragma unroll
        for (int dt = 0; dt < 8; dt++) {
            o[dt][0] *= al0; o[dt][1] *= al0;
            o[dt][2] *= al1; o[dt][3] *= al1;
        }

        #pragma unroll
        for (int nt = 0; nt < 8; nt++) {
            float* pp = Ps + g * ALD + nt * 8 + t * 2;
            pp[0] = tf32r(s[nt][0]); pp[1] = tf32r(s[nt][1]);
            pp[8 * ALD] = tf32r(s[nt][2]); pp[8 * ALD + 1] = tf32r(s[nt][3]);
        }
        __syncwarp();

        #pragma unroll
        for (int ks = 0; ks < 8; ks++) {
            unsigned a[4];
            const float* ap = Ps + g * ALD + ks * 8 + t;
            a[0] = __float_as_uint(ap[0]);
            a[1] = __float_as_uint(ap[8 * ALD]);
            a[2] = __float_as_uint(ap[4]);
            a[3] = __float_as_uint(ap[8 * ALD + 4]);
            #pragma unroll
            for (int dt = 0; dt < 8; dt++) {
                unsigned bb[2];
                const float* bp = Vs + (ks * 8 + t) * ALD + dt * 8 + g;
                bb[0] = __float_as_uint(bp[0]);
                bb[1] = __float_as_uint(bp[4 * ALD]);
                mma8(o[dt], a, bb);
            }
        }
        __syncwarp();
    }

    const float i0 = 1.0f / l0, i1 = 1.0f / l1;
    #pragma unroll
    for (int dt = 0; dt < 8; dt++) {
        int col = dt * 8 + t * 2;
        size_t off0 = obase + (size_t)r0g * EMB + col;
        size_t off1 = obase + (size_t)(r0g + 8) * EMB + col;
        *(float2*)(O + off0) = make_float2(tf32r(o[dt][0] * i0), tf32r(o[dt][1] * i0));
        *(float2*)(O + off1) = make_float2(tf32r(o[dt][2] * i1), tf32r(o[dt][3] * i1));
    }
}

// -------------------- launch --------------------
extern "C" void kernel_launch(void* const* d_in, const int* in_sizes, int n_in,
                              void* d_out, int out_size)
{
    const float* x     = (const float*)d_in[0];
    const float* w_q   = (const float*)d_in[1];
    const float* w_k   = (const float*)d_in[2];
    const float* w_v   = (const float*)d_in[3];
    const float* w_o   = (const float*)d_in[4];
    const float* b_o   = (const float*)d_in[5];
    const float* ln1s  = (const float*)d_in[6];
    const float* ln1b  = (const float*)d_in[7];
    const float* ln2s  = (const float*)d_in[8];
    const float* ln2b  = (const float*)d_in[9];
    const float* w_ff1 = (const float*)d_in[10];
    const float* b_ff1 = (const float*)d_in[11];
    const float* w_ff2 = (const float*)d_in[12];
    const float* b_ff2 = (const float*)d_in[13];
    float* out = (float*)d_out;

    float *ln, *qkv, *ctx, *x1, *ff, *wqkv, *wo, *wf1, *wf2;
    cudaGetSymbolAddress((void**)&ln,   g_ln);
    cudaGetSymbolAddress((void**)&qkv,  g_qkv);
    cudaGetSymbolAddress((void**)&ctx,  g_ctx);
    cudaGetSymbolAddress((void**)&x1,   g_x1);
    cudaGetSymbolAddress((void**)&ff,   g_ff);
    cudaGetSymbolAddress((void**)&wqkv, g_wqkv);
    cudaGetSymbolAddress((void**)&wo,   g_wo);
    cudaGetSymbolAddress((void**)&wf1,  g_wf1);
    cudaGetSymbolAddress((void**)&wf2,  g_wf2);

    cudaFuncSetAttribute((const void*)gemm_kernel<EP_NONE>,
                         cudaFuncAttributeMaxDynamicSharedMemorySize, GEMM_SMEM);
    cudaFuncSetAttribute((const void*)gemm_kernel<EP_BIAS_RES>,
                         cudaFuncAttributeMaxDynamicSharedMemorySize, GEMM_SMEM);
    cudaFuncSetAttribute((const void*)gemm_kernel<EP_BIAS_GELU>,
                         cudaFuncAttributeMaxDynamicSharedMemorySize, GEMM_SMEM);
    cudaFuncSetAttribute((const void*)attn_kernel,
                         cudaFuncAttributeMaxDynamicSharedMemorySize, ATT_SMEM);

    // tf32-round weights once per call (concat QKV along N)
    const int t4_1M = EMB * EMB / 4;          // 262144
    const int t4_4M = EMB * FFDIM / 4;        // 1048576
    round_strided<<<(t4_1M + 255) / 256, 256>>>(w_q, wqkv,            EMB, 3 * EMB, t4_1M);
    round_strided<<<(t4_1M + 255) / 256, 256>>>(w_k, wqkv + EMB,      EMB, 3 * EMB, t4_1M);
    round_strided<<<(t4_1M + 255) / 256, 256>>>(w_v, wqkv + 2 * EMB,  EMB, 3 * EMB, t4_1M);
    round_strided<<<(t4_1M + 255) / 256, 256>>>(w_o, wo,   EMB,   EMB,   t4_1M);
    round_strided<<<(t4_4M + 255) / 256, 256>>>(w_ff1, wf1, FFDIM, FFDIM, t4_4M);
    round_strided<<<(t4_4M + 255) / 256, 256>>>(w_ff2, wf2, EMB,   EMB,   t4_4M);

    // h = LN1(x)
    ln_kernel<<<NROWS, 256>>>(x, ln1s, ln1b, ln);
    // qkv = h @ [Wq|Wk|Wv]
    gemm_kernel<EP_NONE><<<dim3(3 * EMB / BN, NROWS / BM), 256, GEMM_SMEM>>>(
        ln, wqkv, nullptr, nullptr, qkv, NROWS, 3 * EMB, EMB);
    // ctx = causal attention (strided views into qkv)
    attn_kernel<<<dim3(SEQ / 64, BATCH * NHEADS), 128, ATT_SMEM>>>(
        qkv, qkv + EMB, qkv + 2 * EMB, ctx, 3 * EMB);
    // x1 = x + ctx @ w_o + b_o
    gemm_kernel<EP_BIAS_RES><<<dim3(EMB / BN, NROWS / BM), 256, GEMM_SMEM>>>(
        ctx, wo, b_o, x, x1, NROWS, EMB, EMB);
    // h = LN2(x1)
    ln_kernel<<<NROWS, 256>>>(x1, ln2s, ln2b, ln);
    // ff = gelu(h @ w_ff1 + b_ff1)
    gemm_kernel<EP_BIAS_GELU><<<dim3(FFDIM / BN, NROWS / BM), 256, GEMM_SMEM>>>(
        ln, wf1, b_ff1, nullptr, ff, NROWS, FFDIM, EMB);
    // out = x1 + ff @ w_ff2 + b_ff2
    gemm_kernel<EP_BIAS_RES><<<dim3(EMB / BN, NROWS / BM), 256, GEMM_SMEM>>>(
        ff, wf2, b_ff2, x1, out, NROWS, EMB, FFDIM);
}

// round 5
// speedup vs baseline: 1.8293x; 1.5443x over previous
#include <cuda_runtime.h>
#include <cuda_fp16.h>
#include <cstdint>
#include <math.h>

#define EMB 1024
#define SEQ 2048
#define BATCH 2
#define NROWS 4096          // BATCH*SEQ
#define FFDIM 4096
#define NHEADS 16
#define HDIM 64

// -------------------- scratch (no allocation allowed) --------------------
__device__ unsigned short g_ln16 [NROWS * EMB];
__device__ unsigned short g_qkv16[(size_t)NROWS * 3 * EMB];
__device__ unsigned short g_ctx16[NROWS * EMB];
__device__ unsigned short g_ff16 [(size_t)NROWS * FFDIM];
__device__ float          g_x1   [NROWS * EMB];
__device__ unsigned short g_wqkv16[(size_t)EMB * 3 * EMB];
__device__ unsigned short g_wo16  [(size_t)EMB * EMB];
__device__ unsigned short g_wf116 [(size_t)EMB * FFDIM];
__device__ unsigned short g_wf216 [(size_t)FFDIM * EMB];

// -------------------- helpers --------------------
__device__ __forceinline__ float tf32r(float x) {
    unsigned u;
    asm("cvt.rna.tf32.f32 %0, %1;" : "=r"(u) : "f"(x));
    return __uint_as_float(u);
}

__device__ __forceinline__ float gelu_f(float v) {
    float u = v + 0.044715f * v * v * v;
    return 0.5f * v * (1.0f + tanhf(0.7978845608028654f * u));
}

__device__ __forceinline__ uint32_t smem_u32(const void* p) {
    uint32_t a;
    asm("{ .reg .u64 t; cvta.to.shared.u64 t, %1; cvt.u32.u64 %0, t; }" : "=r"(a) : "l"(p));
    return a;
}

// fp16 mma: D(f32) += A(f16) B(f16)
__device__ __forceinline__ void mma16(float* c, const unsigned* a, const unsigned* b) {
    asm volatile(
        "mma.sync.aligned.m16n8k16.row.col.f32.f16.f16.f32 "
        "{%0,%1,%2,%3}, {%4,%5,%6,%7}, {%8,%9}, {%0,%1,%2,%3};\n"
        : "+f"(c[0]), "+f"(c[1]), "+f"(c[2]), "+f"(c[3])
        : "r"(a[0]), "r"(a[1]), "r"(a[2]), "r"(a[3]),
          "r"(b[0]), "r"(b[1]));
}

// tf32 mma (attention)
__device__ __forceinline__ void mma8(float* c, const unsigned* a, const unsigned* b) {
    asm volatile(
        "mma.sync.aligned.m16n8k8.row.col.f32.tf32.tf32.f32 "
        "{%0,%1,%2,%3}, {%4,%5,%6,%7}, {%8,%9}, {%0,%1,%2,%3};\n"
        : "+f"(c[0]), "+f"(c[1]), "+f"(c[2]), "+f"(c[3])
        : "r"(a[0]), "r"(a[1]), "r"(a[2]), "r"(a[3]),
          "r"(b[0]), "r"(b[1]));
}

__device__ __forceinline__ void ldsm4(unsigned& r0, unsigned& r1, unsigned& r2, unsigned& r3,
                                      uint32_t addr) {
    asm volatile("ldmatrix.sync.aligned.m8n8.x4.shared.b16 {%0,%1,%2,%3}, [%4];"
                 : "=r"(r0), "=r"(r1), "=r"(r2), "=r"(r3) : "r"(addr));
}
__device__ __forceinline__ void ldsm4t(unsigned& r0, unsigned& r1, unsigned& r2, unsigned& r3,
                                       uint32_t addr) {
    asm volatile("ldmatrix.sync.aligned.m8n8.x4.trans.shared.b16 {%0,%1,%2,%3}, [%4];"
                 : "=r"(r0), "=r"(r1), "=r"(r2), "=r"(r3) : "r"(addr));
}

// ---- cp.async ----
__device__ __forceinline__ void cpa16(uint32_t dst, const void* src) {
    asm volatile("cp.async.cg.shared.global [%0], [%1], 16;" :: "r"(dst), "l"(src));
}
#define CPA_COMMIT() asm volatile("cp.async.commit_group;" ::: "memory")
template<int N> __device__ __forceinline__ void cpa_wait() {
    asm volatile("cp.async.wait_group %0;" :: "n"(N) : "memory");
}

// -------------------- f32 -> f16 weight conversion (strided dest) ----------
__global__ void __launch_bounds__(256)
round_h(const float* __restrict__ in, __half* __restrict__ out,
        int cols, int ldo, int total4)
{
    int idx = blockIdx.x * 256 + threadIdx.x;
    if (idx >= total4) return;
    int c4 = cols >> 2;
    int r = idx / c4, c = (idx - r * c4) * 4;
    float4 v = *(const float4*)(in + (size_t)r * cols + c);
    __half2 h0 = __floats2half2_rn(v.x, v.y);
    __half2 h1 = __floats2half2_rn(v.z, v.w);
    __half2* o = (__half2*)(out + (size_t)r * ldo + c);
    o[0] = h0; o[1] = h1;
}

// -------------------- layernorm (fp16 output) -------------------------------
__global__ void __launch_bounds__(256)
ln16_kernel(const float* __restrict__ x, const float* __restrict__ sc,
            const float* __restrict__ sh, __half* __restrict__ out)
{
    __shared__ float red[8];
    __shared__ float stats[2];
    const int row = blockIdx.x, tid = threadIdx.x, lane = tid & 31, warp = tid >> 5;
    const float* xr = x + (size_t)row * EMB;
    float4 v = *(const float4*)(xr + tid * 4);

    float s = v.x + v.y + v.z + v.w;
    #pragma unroll
    for (int o = 16; o > 0; o >>= 1) s += __shfl_xor_sync(0xffffffffu, s, o);
    if (lane == 0) red[warp] = s;
    __syncthreads();
    if (tid == 0) {
        float t = 0.f;
        #pragma unroll
        for (int i = 0; i < 8; i++) t += red[i];
        stats[0] = t * (1.0f / EMB);
    }
    __syncthreads();
    const float mean = stats[0];
    float dx = v.x - mean, dy = v.y - mean, dz = v.z - mean, dw = v.w - mean;
    float ss = dx * dx + dy * dy + dz * dz + dw * dw;
    #pragma unroll
    for (int o = 16; o > 0; o >>= 1) ss += __shfl_xor_sync(0xffffffffu, ss, o);
    if (lane == 0) red[warp] = ss;
    __syncthreads();
    if (tid == 0) {
        float t = 0.f;
        #pragma unroll
        for (int i = 0; i < 8; i++) t += red[i];
        stats[1] = rsqrtf(t * (1.0f / EMB) + 1e-5f);
    }
    __syncthreads();
    const float rstd = stats[1];
    float4 scv = *(const float4*)(sc + tid * 4);
    float4 shv = *(const float4*)(sh + tid * 4);
    __half2 h0 = __floats2half2_rn(scv.x * dx * rstd + shv.x, scv.y * dy * rstd + shv.y);
    __half2 h1 = __floats2half2_rn(scv.z * dz * rstd + shv.z, scv.w * dw * rstd + shv.w);
    __half2* o = (__half2*)(out + (size_t)row * EMB + tid * 4);
    o[0] = h0; o[1] = h1;
}

// -------------------- fp16 GEMM (m16n8k16, 128x128x64, 3-stage cp.async) ---
// A [M][K] f16 row-major, B [K][N] f16 row-major. 4 warps, 64x64 warp tile.
#define BM 128
#define BN 128
#define BK 64
#define A_ROW_B 144           // (64+8) halves * 2B
#define B_ROW_B 272           // (128+8) halves * 2B
#define ASTG (BM * A_ROW_B)   // 18432
#define BSTG (BK * B_ROW_B)   // 17408
#define STGB (ASTG + BSTG)    // 35840
#define GEMM_SMEM (3 * STGB)  // 107520

enum { EP_H = 0, EP_GELU_H = 1, EP_RES_F = 2 };

__device__ __forceinline__ void fill_stage16(uint32_t sA, uint32_t sB,
                                             const __half* __restrict__ A,
                                             const __half* __restrict__ B,
                                             int bm, int bn, int N, int K, int kc, int tid)
{
    #pragma unroll
    for (int i = 0; i < 8; i++) {
        int e = tid + i * 128;
        int row = e >> 3, seg = e & 7;
        cpa16(sA + row * A_ROW_B + seg * 16,
              A + (size_t)(bm + row) * K + kc * BK + seg * 8);
    }
    #pragma unroll
    for (int i = 0; i < 8; i++) {
        int e = tid + i * 128;
        int row = e >> 4, seg = e & 15;
        cpa16(sB + row * B_ROW_B + seg * 16,
              B + (size_t)(kc * BK + row) * N + bn + seg * 8);
    }
}

template<int EPI>
__global__ void __launch_bounds__(128, 2)
gemm16(const __half* __restrict__ A, const __half* __restrict__ B,
       const float* __restrict__ bias, const float* __restrict__ R,
       void* __restrict__ Cv, int M, int N, int K)
{
    extern __shared__ char smem[];
    const uint32_t sbase = smem_u32(smem);

    const int tid = threadIdx.x, lane = tid & 31, warp = tid >> 5;
    const int bm = blockIdx.y * BM, bn = blockIdx.x * BN;
    const int wm = (warp & 1) * 64, wn = (warp >> 1) * 64;
    const int g = lane >> 2, t = lane & 3;
    const int NK = K / BK;

    float c[4][8][4];
    #pragma unroll
    for (int mt = 0; mt < 4; mt++)
        #pragma unroll
        for (int nt = 0; nt < 8; nt++)
            #pragma unroll
            for (int e = 0; e < 4; e++) c[mt][nt][e] = 0.f;

    fill_stage16(sbase,        sbase + ASTG,        A, B, bm, bn, N, K, 0, tid);
    CPA_COMMIT();
    fill_stage16(sbase + STGB, sbase + STGB + ASTG, A, B, bm, bn, N, K, 1, tid);
    CPA_COMMIT();

    // ldmatrix lane bases (within current stage)
    const uint32_t laoff = (wm + (lane & 15)) * A_ROW_B + (lane >> 4) * 16;
    const uint32_t lboff = (lane & 15) * B_ROW_B + (lane >> 4) * 16 + wn * 2;

    int stg = 0;
    for (int kt = 0; kt < NK; kt++) {
        if (kt == NK - 1) cpa_wait<0>(); else cpa_wait<1>();
        __syncthreads();

        if (kt + 2 < NK) {
            int fs = kt + 2; fs -= (fs / 3) * 3;
            fill_stage16(sbase + fs * STGB, sbase + fs * STGB + ASTG,
                         A, B, bm, bn, N, K, kt + 2, tid);
            CPA_COMMIT();
        }

        const uint32_t sA = sbase + stg * STGB;
        const uint32_t sB = sA + ASTG;
        const uint32_t la = sA + laoff;
        const uint32_t lb = sB + lboff;

        #pragma unroll
        for (int ks = 0; ks < 4; ks++) {           // 4 x k16
            unsigned a[4][4], b[8][2];
            #pragma unroll
            for (int mt = 0; mt < 4; mt++)
                ldsm4(a[mt][0], a[mt][1], a[mt][2], a[mt][3],
                      la + mt * (16 * A_ROW_B) + ks * 32);
            #pragma unroll
            for (int np = 0; np < 4; np++) {
                unsigned r0, r1, r2, r3;
                ldsm4t(r0, r1, r2, r3, lb + ks * (16 * B_ROW_B) + np * 32);
                b[2 * np][0] = r0;     b[2 * np][1] = r1;
                b[2 * np + 1][0] = r2; b[2 * np + 1][1] = r3;
            }
            #pragma unroll
            for (int mt = 0; mt < 4; mt++)
                #pragma unroll
                for (int nt = 0; nt < 8; nt++)
                    mma16(c[mt][nt], a[mt], b[nt]);
        }

        stg++; if (stg == 3) stg = 0;
    }

    // epilogue
    #pragma unroll
    for (int mt = 0; mt < 4; mt++) {
        #pragma unroll
        for (int nt = 0; nt < 8; nt++) {
            const int row0 = bm + wm + mt * 16 + g;
            const int col  = bn + wn + nt * 8 + t * 2;
            #pragma unroll
            for (int h = 0; h < 2; h++) {
                const int row = row0 + h * 8;
                float v0 = c[mt][nt][2 * h], v1 = c[mt][nt][2 * h + 1];
                const size_t off = (size_t)row * N + col;
                if (EPI == EP_H) {
                    *(__half2*)((__half*)Cv + off) = __floats2half2_rn(v0, v1);
                } else if (EPI == EP_GELU_H) {
                    float2 bb = *(const float2*)(bias + col);
                    *(__half2*)((__half*)Cv + off) =
                        __floats2half2_rn(gelu_f(v0 + bb.x), gelu_f(v1 + bb.y));
                } else {  // EP_RES_F
                    float2 bb = *(const float2*)(bias + col);
                    float2 rr = *(const float2*)(R + off);
                    *(float2*)((float*)Cv + off) =
                        make_float2(v0 + bb.x + rr.x, v1 + bb.y + rr.y);
                }
            }
        }
    }
}

// -------------------- causal flash attention (Br=Bc=64, d=64) --------------
// fp16 inputs (strided views into qkv), fp16 output; tf32 mma internally.
#define ALD 68
#define ATT_SMEM ((3 * 64 * ALD + 4 * 16 * ALD) * 4)

__global__ void __launch_bounds__(128)
attn_kernel(const __half* __restrict__ Q, const __half* __restrict__ Kg,
            const __half* __restrict__ Vg, __half* __restrict__ O, int ldq)
{
    extern __shared__ float sm[];
    float* Qs = sm;
    float* Ks = sm + 64 * ALD;
    float* Vs = sm + 2 * 64 * ALD;

    const int tid = threadIdx.x, lane = tid & 31, warp = tid >> 5;
    const int g = lane >> 2, t = lane & 3;
    float* Ps = sm + 3 * 64 * ALD + warp * 16 * ALD;

    const int qt = blockIdx.x;
    const int bh = blockIdx.y;
    const int b = bh >> 4, h = bh & 15;
    const size_t base  = (size_t)b * SEQ * ldq + (size_t)h * HDIM;
    const size_t obase = (size_t)b * SEQ * EMB + (size_t)h * HDIM;

    #pragma unroll
    for (int i = 0; i < 8; i++) {
        int idx = tid + i * 128, r = idx >> 4, c = (idx & 15) * 4;
        const __half2* qp = (const __half2*)(Q + base + (size_t)(qt * 64 + r) * ldq + c);
        float2 f0 = __half22float2(qp[0]), f1 = __half22float2(qp[1]);
        float* d = Qs + r * ALD + c;
        d[0] = f0.x; d[1] = f0.y; d[2] = f1.x; d[3] = f1.y;
    }

    float m0 = -1e30f, m1 = -1e30f, l0 = 0.f, l1 = 0.f;
    float o[8][4];
    #pragma unroll
    for (int dt = 0; dt < 8; dt++)
        #pragma unroll
        for (int e = 0; e < 4; e++) o[dt][e] = 0.f;

    const int r0g = qt * 64 + warp * 16 + g;

    for (int j = 0; j <= qt; j++) {
        __syncthreads();
        #pragma unroll
        for (int i = 0; i < 8; i++) {
            int idx = tid + i * 128, r = idx >> 4, c = (idx & 15) * 4;
            size_t go = base + (size_t)(j * 64 + r) * ldq + c;
            const __half2* kp = (const __half2*)(Kg + go);
            const __half2* vp = (const __half2*)(Vg + go);
            float2 k0 = __half22float2(kp[0]), k1 = __half22float2(kp[1]);
            float2 v0 = __half22float2(vp[0]), v1 = __half22float2(vp[1]);
            float* dk = Ks + r * ALD + c;
            dk[0] = k0.x; dk[1] = k0.y; dk[2] = k1.x; dk[3] = k1.y;
            float* dv = Vs + r * ALD + c;
            dv[0] = v0.x; dv[1] = v0.y; dv[2] = v1.x; dv[3] = v1.y;
        }
        __syncthreads();

        float s[8][4];
        #pragma unroll
        for (int nt = 0; nt < 8; nt++)
            #pragma unroll
            for (int e = 0; e < 4; e++) s[nt][e] = 0.f;

        #pragma unroll
        for (int ks = 0; ks < 8; ks++) {
            unsigned a[4];
            const float* ap = Qs + (warp * 16 + g) * ALD + ks * 8 + t;
            a[0] = __float_as_uint(ap[0]);
            a[1] = __float_as_uint(ap[8 * ALD]);
            a[2] = __float_as_uint(ap[4]);
            a[3] = __float_as_uint(ap[8 * ALD + 4]);
            #pragma unroll
            for (int nt = 0; nt < 8; nt++) {
                unsigned bb[2];
                const float* bp = Ks + (nt * 8 + g) * ALD + ks * 8 + t;
                bb[0] = __float_as_uint(bp[0]);
                bb[1] = __float_as_uint(bp[4]);
                mma8(s[nt], a, bb);
            }
        }

        #pragma unroll
        for (int nt = 0; nt < 8; nt++)
            #pragma unroll
            for (int e = 0; e < 4; e++) s[nt][e] *= 0.125f;
        if (j == qt) {
            #pragma unroll
            for (int nt = 0; nt < 8; nt++) {
                int cb = j * 64 + nt * 8 + t * 2;
                if (cb     > r0g)     s[nt][0] = -1e30f;
                if (cb + 1 > r0g)     s[nt][1] = -1e30f;
                if (cb     > r0g + 8) s[nt][2] = -1e30f;
                if (cb + 1 > r0g + 8) s[nt][3] = -1e30f;
            }
        }

        float t0 = -1e30f, t1 = -1e30f;
        #pragma unroll
        for (int nt = 0; nt < 8; nt++) {
            t0 = fmaxf(t0, fmaxf(s[nt][0], s[nt][1]));
            t1 = fmaxf(t1, fmaxf(s[nt][2], s[nt][3]));
        }
        t0 = fmaxf(t0, __shfl_xor_sync(0xffffffffu, t0, 1));
        t0 = fmaxf(t0, __shfl_xor_sync(0xffffffffu, t0, 2));
        t1 = fmaxf(t1, __shfl_xor_sync(0xffffffffu, t1, 1));
        t1 = fmaxf(t1, __shfl_xor_sync(0xffffffffu, t1, 2));
        float mn0 = fmaxf(m0, t0), mn1 = fmaxf(m1, t1);
        float al0 = __expf(m0 - mn0), al1 = __expf(m1 - mn1);
        float su0 = 0.f, su1 = 0.f;
        #pragma unroll
        for (int nt = 0; nt < 8; nt++) {
            s[nt][0] = __expf(s[nt][0] - mn0); su0 += s[nt][0];
            s[nt][1] = __expf(s[nt][1] - mn0); su0 += s[nt][1];
            s[nt][2] = __expf(s[nt][2] - mn1); su1 += s[nt][2];
            s[nt][3] = __expf(s[nt][3] - mn1); su1 += s[nt][3];
        }
        su0 += __shfl_xor_sync(0xffffffffu, su0, 1);
        su0 += __shfl_xor_sync(0xffffffffu, su0, 2);
        su1 += __shfl_xor_sync(0xffffffffu, su1, 1);
        su1 += __shfl_xor_sync(0xffffffffu, su1, 2);
        l0 = l0 * al0 + su0; l1 = l1 * al1 + su1;
        m0 = mn0; m1 = mn1;
        #pragma unroll
        for (int dt = 0; dt < 8; dt++) {
            o[dt][0] *= al0; o[dt][1] *= al0;
            o[dt][2] *= al1; o[dt][3] *= al1;
        }

        #pragma unroll
        for (int nt = 0; nt < 8; nt++) {
            float* pp = Ps + g * ALD + nt * 8 + t * 2;
            pp[0] = tf32r(s[nt][0]); pp[1] = tf32r(s[nt][1]);
            pp[8 * ALD] = tf32r(s[nt][2]); pp[8 * ALD + 1] = tf32r(s[nt][3]);
        }
        __syncwarp();

        #pragma unroll
        for (int ks = 0; ks < 8; ks++) {
            unsigned a[4];
            const float* ap = Ps + g * ALD + ks * 8 + t;
            a[0] = __float_as_uint(ap[0]);
            a[1] = __float_as_uint(ap[8 * ALD]);
            a[2] = __float_as_uint(ap[4]);
            a[3] = __float_as_uint(ap[8 * ALD + 4]);
            #pragma unroll
            for (int dt = 0; dt < 8; dt++) {
                unsigned bb[2];
                const float* bp = Vs + (ks * 8 + t) * ALD + dt * 8 + g;
                bb[0] = __float_as_uint(bp[0]);
                bb[1] = __float_as_uint(bp[4 * ALD]);
                mma8(o[dt], a, bb);
            }
        }
        __syncwarp();
    }

    const float i0 = 1.0f / l0, i1 = 1.0f / l1;
    #pragma unroll
    for (int dt = 0; dt < 8; dt++) {
        int col = dt * 8 + t * 2;
        size_t off0 = obase + (size_t)r0g * EMB + col;
        size_t off1 = obase + (size_t)(r0g + 8) * EMB + col;
        *(__half2*)(O + off0) = __floats2half2_rn(o[dt][0] * i0, o[dt][1] * i0);
        *(__half2*)(O + off1) = __floats2half2_rn(o[dt][2] * i1, o[dt][3] * i1);
    }
}

// -------------------- launch --------------------
extern "C" void kernel_launch(void* const* d_in, const int* in_sizes, int n_in,
                              void* d_out, int out_size)
{
    const float* x     = (const float*)d_in[0];
    const float* w_q   = (const float*)d_in[1];
    const float* w_k   = (const float*)d_in[2];
    const float* w_v   = (const float*)d_in[3];
    const float* w_o   = (const float*)d_in[4];
    const float* b_o   = (const float*)d_in[5];
    const float* ln1s  = (const float*)d_in[6];
    const float* ln1b  = (const float*)d_in[7];
    const float* ln2s  = (const float*)d_in[8];
    const float* ln2b  = (const float*)d_in[9];
    const float* w_ff1 = (const float*)d_in[10];
    const float* b_ff1 = (const float*)d_in[11];
    const float* w_ff2 = (const float*)d_in[12];
    const float* b_ff2 = (const float*)d_in[13];
    float* out = (float*)d_out;

    void *p;
    cudaGetSymbolAddress(&p, g_ln16);   __half* ln16   = (__half*)p;
    cudaGetSymbolAddress(&p, g_qkv16);  __half* qkv16  = (__half*)p;
    cudaGetSymbolAddress(&p, g_ctx16);  __half* ctx16  = (__half*)p;
    cudaGetSymbolAddress(&p, g_ff16);   __half* ff16   = (__half*)p;
    cudaGetSymbolAddress(&p, g_x1);     float*  x1     = (float*)p;
    cudaGetSymbolAddress(&p, g_wqkv16); __half* wqkv16 = (__half*)p;
    cudaGetSymbolAddress(&p, g_wo16);   __half* wo16   = (__half*)p;
    cudaGetSymbolAddress(&p, g_wf116);  __half* wf116  = (__half*)p;
    cudaGetSymbolAddress(&p, g_wf216);  __half* wf216  = (__half*)p;

    cudaFuncSetAttribute((const void*)gemm16<EP_H>,
                         cudaFuncAttributeMaxDynamicSharedMemorySize, GEMM_SMEM);
    cudaFuncSetAttribute((const void*)gemm16<EP_GELU_H>,
                         cudaFuncAttributeMaxDynamicSharedMemorySize, GEMM_SMEM);
    cudaFuncSetAttribute((const void*)gemm16<EP_RES_F>,
                         cudaFuncAttributeMaxDynamicSharedMemorySize, GEMM_SMEM);
    cudaFuncSetAttribute((const void*)attn_kernel,
                         cudaFuncAttributeMaxDynamicSharedMemorySize, ATT_SMEM);

    // weights -> fp16 (QKV concatenated along N)
    const int t4_1M = EMB * EMB / 4;
    const int t4_4M = EMB * FFDIM / 4;
    round_h<<<(t4_1M + 255) / 256, 256>>>(w_q, wqkv16,           EMB, 3 * EMB, t4_1M);
    round_h<<<(t4_1M + 255) / 256, 256>>>(w_k, wqkv16 + EMB,     EMB, 3 * EMB, t4_1M);
    round_h<<<(t4_1M + 255) / 256, 256>>>(w_v, wqkv16 + 2 * EMB, EMB, 3 * EMB, t4_1M);
    round_h<<<(t4_1M + 255) / 256, 256>>>(w_o,   wo16,  EMB,   EMB,   t4_1M);
    round_h<<<(t4_4M + 255) / 256, 256>>>(w_ff1, wf116, FFDIM, FFDIM, t4_4M);
    round_h<<<(t4_4M + 255) / 256, 256>>>(w_ff2, wf216, EMB,   EMB,   t4_4M);

    // h = LN1(x)  (fp16 out)
    ln16_kernel<<<NROWS, 256>>>(x, ln1s, ln1b, ln16);
    // qkv(f16) = h @ [Wq|Wk|Wv]
    gemm16<EP_H><<<dim3(3 * EMB / BN, NROWS / BM), 128, GEMM_SMEM>>>(
        ln16, wqkv16, nullptr, nullptr, qkv16, NROWS, 3 * EMB, EMB);
    // ctx(f16) = causal attention
    attn_kernel<<<dim3(SEQ / 64, BATCH * NHEADS), 128, ATT_SMEM>>>(
        qkv16, qkv16 + EMB, qkv16 + 2 * EMB, ctx16, 3 * EMB);
    // x1(f32) = x + ctx @ w_o + b_o
    gemm16<EP_RES_F><<<dim3(EMB / BN, NROWS / BM), 128, GEMM_SMEM>>>(
        ctx16, wo16, b_o, x, x1, NROWS, EMB, EMB);
    // h = LN2(x1)  (fp16 out)
    ln16_kernel<<<NROWS, 256>>>(x1, ln2s, ln2b, ln16);
    // ff(f16) = gelu(h @ w_ff1 + b_ff1)
    gemm16<EP_GELU_H><<<dim3(FFDIM / BN, NROWS / BM), 128, GEMM_SMEM>>>(
        ln16, wf116, b_ff1, nullptr, ff16, NROWS, FFDIM, EMB);
    // out(f32) = x1 + ff @ w_ff2 + b_ff2
    gemm16<EP_RES_F><<<dim3(EMB / BN, NROWS / BM), 128, GEMM_SMEM>>>(
        ff16, wf216, b_ff2, x1, out, NROWS, EMB, FFDIM);
}

// round 6
// speedup vs baseline: 2.3208x; 1.2686x over previous
#include <cuda_runtime.h>
#include <cuda_fp16.h>
#include <cstdint>
#include <math.h>

#define EMB 1024
#define SEQ 2048
#define BATCH 2
#define NROWS 4096          // BATCH*SEQ
#define FFDIM 4096
#define NHEADS 16
#define HDIM 64

// -------------------- scratch (no allocation allowed) --------------------
__device__ unsigned short g_ln16 [NROWS * EMB];
__device__ unsigned short g_qkv16[(size_t)NROWS * 3 * EMB];
__device__ unsigned short g_ctx16[NROWS * EMB];
__device__ unsigned short g_ff16 [(size_t)NROWS * FFDIM];
__device__ float          g_x1   [NROWS * EMB];
__device__ unsigned short g_wqkv16[(size_t)EMB * 3 * EMB];
__device__ unsigned short g_wo16  [(size_t)EMB * EMB];
__device__ unsigned short g_wf116 [(size_t)EMB * FFDIM];
__device__ unsigned short g_wf216 [(size_t)FFDIM * EMB];

// -------------------- helpers --------------------
__device__ __forceinline__ float gelu_f(float v) {
    float u = v + 0.044715f * v * v * v;
    return 0.5f * v * (1.0f + tanhf(0.7978845608028654f * u));
}

__device__ __forceinline__ uint32_t smem_u32(const void* p) {
    uint32_t a;
    asm("{ .reg .u64 t; cvta.to.shared.u64 t, %1; cvt.u32.u64 %0, t; }" : "=r"(a) : "l"(p));
    return a;
}

// pack two f32 -> f16x2 (lo = first arg)
__device__ __forceinline__ unsigned packh2(float lo, float hi) {
    unsigned r;
    asm("cvt.rn.f16x2.f32 %0, %1, %2;" : "=r"(r) : "f"(hi), "f"(lo));
    return r;
}

// fp16 mma: D(f32) += A(f16) B(f16)
__device__ __forceinline__ void mma16(float* c, const unsigned* a, const unsigned* b) {
    asm volatile(
        "mma.sync.aligned.m16n8k16.row.col.f32.f16.f16.f32 "
        "{%0,%1,%2,%3}, {%4,%5,%6,%7}, {%8,%9}, {%0,%1,%2,%3};\n"
        : "+f"(c[0]), "+f"(c[1]), "+f"(c[2]), "+f"(c[3])
        : "r"(a[0]), "r"(a[1]), "r"(a[2]), "r"(a[3]),
          "r"(b[0]), "r"(b[1]));
}

__device__ __forceinline__ void ldsm4(unsigned& r0, unsigned& r1, unsigned& r2, unsigned& r3,
                                      uint32_t addr) {
    asm volatile("ldmatrix.sync.aligned.m8n8.x4.shared.b16 {%0,%1,%2,%3}, [%4];"
                 : "=r"(r0), "=r"(r1), "=r"(r2), "=r"(r3) : "r"(addr));
}
__device__ __forceinline__ void ldsm4t(unsigned& r0, unsigned& r1, unsigned& r2, unsigned& r3,
                                       uint32_t addr) {
    asm volatile("ldmatrix.sync.aligned.m8n8.x4.trans.shared.b16 {%0,%1,%2,%3}, [%4];"
                 : "=r"(r0), "=r"(r1), "=r"(r2), "=r"(r3) : "r"(addr));
}

// ---- cp.async ----
__device__ __forceinline__ void cpa16(uint32_t dst, const void* src) {
    asm volatile("cp.async.cg.shared.global [%0], [%1], 16;" :: "r"(dst), "l"(src));
}
#define CPA_COMMIT() asm volatile("cp.async.commit_group;" ::: "memory")
template<int N> __device__ __forceinline__ void cpa_wait() {
    asm volatile("cp.async.wait_group %0;" :: "n"(N) : "memory");
}

// -------------------- f32 -> f16 weight conversion (strided dest) ----------
__global__ void __launch_bounds__(256)
round_h(const float* __restrict__ in, __half* __restrict__ out,
        int cols, int ldo, int total4)
{
    int idx = blockIdx.x * 256 + threadIdx.x;
    if (idx >= total4) return;
    int c4 = cols >> 2;
    int r = idx / c4, c = (idx - r * c4) * 4;
    float4 v = *(const float4*)(in + (size_t)r * cols + c);
    __half2 h0 = __floats2half2_rn(v.x, v.y);
    __half2 h1 = __floats2half2_rn(v.z, v.w);
    __half2* o = (__half2*)(out + (size_t)r * ldo + c);
    o[0] = h0; o[1] = h1;
}

// -------------------- layernorm (fp16 output) -------------------------------
__global__ void __launch_bounds__(256)
ln16_kernel(const float* __restrict__ x, const float* __restrict__ sc,
            const float* __restrict__ sh, __half* __restrict__ out)
{
    __shared__ float red[8];
    __shared__ float stats[2];
    const int row = blockIdx.x, tid = threadIdx.x, lane = tid & 31, warp = tid >> 5;
    const float* xr = x + (size_t)row * EMB;
    float4 v = *(const float4*)(xr + tid * 4);

    float s = v.x + v.y + v.z + v.w;
    #pragma unroll
    for (int o = 16; o > 0; o >>= 1) s += __shfl_xor_sync(0xffffffffu, s, o);
    if (lane == 0) red[warp] = s;
    __syncthreads();
    if (tid == 0) {
        float t = 0.f;
        #pragma unroll
        for (int i = 0; i < 8; i++) t += red[i];
        stats[0] = t * (1.0f / EMB);
    }
    __syncthreads();
    const float mean = stats[0];
    float dx = v.x - mean, dy = v.y - mean, dz = v.z - mean, dw = v.w - mean;
    float ss = dx * dx + dy * dy + dz * dz + dw * dw;
    #pragma unroll
    for (int o = 16; o > 0; o >>= 1) ss += __shfl_xor_sync(0xffffffffu, ss, o);
    if (lane == 0) red[warp] = ss;
    __syncthreads();
    if (tid == 0) {
        float t = 0.f;
        #pragma unroll
        for (int i = 0; i < 8; i++) t += red[i];
        stats[1] = rsqrtf(t * (1.0f / EMB) + 1e-5f);
    }
    __syncthreads();
    const float rstd = stats[1];
    float4 scv = *(const float4*)(sc + tid * 4);
    float4 shv = *(const float4*)(sh + tid * 4);
    __half2 h0 = __floats2half2_rn(scv.x * dx * rstd + shv.x, scv.y * dy * rstd + shv.y);
    __half2 h1 = __floats2half2_rn(scv.z * dz * rstd + shv.z, scv.w * dw * rstd + shv.w);
    __half2* o = (__half2*)(out + (size_t)row * EMB + tid * 4);
    o[0] = h0; o[1] = h1;
}

// -------------------- fp16 GEMM (m16n8k16, 128x128x64, 3-stage cp.async) ---
#define BM 128
#define BN 128
#define BK 64
#define A_ROW_B 144           // (64+8) halves * 2B
#define B_ROW_B 272           // (128+8) halves * 2B
#define ASTG (BM * A_ROW_B)
#define BSTG (BK * B_ROW_B)
#define STGB (ASTG + BSTG)
#define GEMM_SMEM (3 * STGB)

enum { EP_H = 0, EP_GELU_H = 1, EP_RES_F = 2 };

__device__ __forceinline__ void fill_stage16(uint32_t sA, uint32_t sB,
                                             const __half* __restrict__ A,
                                             const __half* __restrict__ B,
                                             int bm, int bn, int N, int K, int kc, int tid)
{
    #pragma unroll
    for (int i = 0; i < 8; i++) {
        int e = tid + i * 128;
        int row = e >> 3, seg = e & 7;
        cpa16(sA + row * A_ROW_B + seg * 16,
              A + (size_t)(bm + row) * K + kc * BK + seg * 8);
    }
    #pragma unroll
    for (int i = 0; i < 8; i++) {
        int e = tid + i * 128;
        int row = e >> 4, seg = e & 15;
        cpa16(sB + row * B_ROW_B + seg * 16,
              B + (size_t)(kc * BK + row) * N + bn + seg * 8);
    }
}

template<int EPI>
__global__ void __launch_bounds__(128, 2)
gemm16(const __half* __restrict__ A, const __half* __restrict__ B,
       const float* __restrict__ bias, const float* __restrict__ R,
       void* __restrict__ Cv, int M, int N, int K)
{
    extern __shared__ char smem[];
    const uint32_t sbase = smem_u32(smem);

    const int tid = threadIdx.x, lane = tid & 31, warp = tid >> 5;
    const int bm = blockIdx.y * BM, bn = blockIdx.x * BN;
    const int wm = (warp & 1) * 64, wn = (warp >> 1) * 64;
    const int g = lane >> 2, t = lane & 3;
    const int NK = K / BK;

    float c[4][8][4];
    #pragma unroll
    for (int mt = 0; mt < 4; mt++)
        #pragma unroll
        for (int nt = 0; nt < 8; nt++)
            #pragma unroll
            for (int e = 0; e < 4; e++) c[mt][nt][e] = 0.f;

    fill_stage16(sbase,        sbase + ASTG,        A, B, bm, bn, N, K, 0, tid);
    CPA_COMMIT();
    fill_stage16(sbase + STGB, sbase + STGB + ASTG, A, B, bm, bn, N, K, 1, tid);
    CPA_COMMIT();

    const uint32_t laoff = (wm + (lane & 15)) * A_ROW_B + (lane >> 4) * 16;
    const uint32_t lboff = (lane & 15) * B_ROW_B + (lane >> 4) * 16 + wn * 2;

    int stg = 0;
    for (int kt = 0; kt < NK; kt++) {
        if (kt == NK - 1) cpa_wait<0>(); else cpa_wait<1>();
        __syncthreads();

        if (kt + 2 < NK) {
            int fs = kt + 2; fs -= (fs / 3) * 3;
            fill_stage16(sbase + fs * STGB, sbase + fs * STGB + ASTG,
                         A, B, bm, bn, N, K, kt + 2, tid);
            CPA_COMMIT();
        }

        const uint32_t sA = sbase + stg * STGB;
        const uint32_t sB = sA + ASTG;
        const uint32_t la = sA + laoff;
        const uint32_t lb = sB + lboff;

        #pragma unroll
        for (int ks = 0; ks < 4; ks++) {
            unsigned a[4][4], b[8][2];
            #pragma unroll
            for (int mt = 0; mt < 4; mt++)
                ldsm4(a[mt][0], a[mt][1], a[mt][2], a[mt][3],
                      la + mt * (16 * A_ROW_B) + ks * 32);
            #pragma unroll
            for (int np = 0; np < 4; np++) {
                unsigned r0, r1, r2, r3;
                ldsm4t(r0, r1, r2, r3, lb + ks * (16 * B_ROW_B) + np * 32);
                b[2 * np][0] = r0;     b[2 * np][1] = r1;
                b[2 * np + 1][0] = r2; b[2 * np + 1][1] = r3;
            }
            #pragma unroll
            for (int mt = 0; mt < 4; mt++)
                #pragma unroll
                for (int nt = 0; nt < 8; nt++)
                    mma16(c[mt][nt], a[mt], b[nt]);
        }

        stg++; if (stg == 3) stg = 0;
    }

    #pragma unroll
    for (int mt = 0; mt < 4; mt++) {
        #pragma unroll
        for (int nt = 0; nt < 8; nt++) {
            const int row0 = bm + wm + mt * 16 + g;
            const int col  = bn + wn + nt * 8 + t * 2;
            #pragma unroll
            for (int h = 0; h < 2; h++) {
                const int row = row0 + h * 8;
                float v0 = c[mt][nt][2 * h], v1 = c[mt][nt][2 * h + 1];
                const size_t off = (size_t)row * N + col;
                if (EPI == EP_H) {
                    *(__half2*)((__half*)Cv + off) = __floats2half2_rn(v0, v1);
                } else if (EPI == EP_GELU_H) {
                    float2 bb = *(const float2*)(bias + col);
                    *(__half2*)((__half*)Cv + off) =
                        __floats2half2_rn(gelu_f(v0 + bb.x), gelu_f(v1 + bb.y));
                } else {
                    float2 bb = *(const float2*)(bias + col);
                    float2 rr = *(const float2*)(R + off);
                    *(float2*)((float*)Cv + off) =
                        make_float2(v0 + bb.x + rr.x, v1 + bb.y + rr.y);
                }
            }
        }
    }
}

// -------------------- fp16 causal flash attention (Br=Bc=64, d=64) ---------
// fp16 mma m16n8k16 for QK^T and PV; P stays in registers (C-frag -> A-frag).
// KV double-buffered cp.async. Q A-frags hoisted out of the j loop.
#define KROW 144                       // (64+8) halves * 2B per row
#define KVTILE (64 * KROW)             // 9216 B per K or V tile
#define ATT_SMEM (KVTILE + 2 * 2 * KVTILE)   // Q + 2 stages of (K,V) = 46080

__global__ void __launch_bounds__(128, 2)
attn16(const __half* __restrict__ Qg, const __half* __restrict__ Kg,
       const __half* __restrict__ Vg, __half* __restrict__ O, int ldq)
{
    extern __shared__ char smem[];
    const uint32_t sbase = smem_u32(smem);
    const uint32_t sQ = sbase;
    // stage s: K at sbase + KVTILE + s*2*KVTILE, V at +KVTILE more

    const int tid = threadIdx.x, lane = tid & 31, warp = tid >> 5;
    const int g = lane >> 2, t = lane & 3;

    const int qt = blockIdx.x;
    const int bh = blockIdx.y;
    const int b = bh >> 4, h = bh & 15;
    const size_t qbase = (size_t)b * SEQ * ldq + (size_t)h * HDIM;
    const size_t obase = (size_t)b * SEQ * EMB + (size_t)h * HDIM;

    // fill K/V tile j into stage s
    auto fill_kv = [&](int s, int j) {
        const uint32_t sK = sbase + KVTILE + s * (2 * KVTILE);
        const uint32_t sV = sK + KVTILE;
        #pragma unroll
        for (int i = 0; i < 4; i++) {
            int e = tid + i * 128;
            int row = e >> 3, seg = e & 7;
            size_t go = qbase + (size_t)(j * 64 + row) * ldq + seg * 8;
            cpa16(sK + row * KROW + seg * 16, Kg + go);
            cpa16(sV + row * KROW + seg * 16, Vg + go);
        }
    };

    fill_kv(0, 0);
    CPA_COMMIT();

    // Q tile -> smem (direct)
    #pragma unroll
    for (int i = 0; i < 4; i++) {
        int e = tid + i * 128;
        int row = e >> 3, seg = e & 7;
        *(uint4*)(smem + row * KROW + seg * 16) =
            *(const uint4*)(Qg + qbase + (size_t)(qt * 64 + row) * ldq + seg * 8);
    }
    __syncthreads();

    // hoist Q A-frags (4 k16-chunks x 4 regs)
    unsigned qa[4][4];
    {
        const uint32_t la = sQ + (warp * 16 + (lane & 15)) * KROW + (lane >> 4) * 16;
        #pragma unroll
        for (int ks = 0; ks < 4; ks++)
            ldsm4(qa[ks][0], qa[ks][1], qa[ks][2], qa[ks][3], la + ks * 32);
    }

    // ldmatrix lane-address offsets inside K (non-trans) and V (trans) tiles
    const uint32_t kboff = ((lane & 7) + ((lane >> 4) << 3)) * KROW + ((lane >> 3) & 1) * 16;
    const uint32_t vboff = (lane & 15) * KROW + (lane >> 4) * 16;

    float m0 = -1e30f, m1 = -1e30f, l0 = 0.f, l1 = 0.f;
    float o[8][4];
    #pragma unroll
    for (int dt = 0; dt < 8; dt++)
        #pragma unroll
        for (int e = 0; e < 4; e++) o[dt][e] = 0.f;

    const int r0g = qt * 64 + warp * 16 + g;

    for (int j = 0; j <= qt; j++) {
        if (j < qt) { fill_kv((j + 1) & 1, j + 1); CPA_COMMIT(); }
        if (j < qt) cpa_wait<1>(); else cpa_wait<0>();
        __syncthreads();

        const uint32_t sK = sbase + KVTILE + (j & 1) * (2 * KVTILE);
        const uint32_t sV = sK + KVTILE;

        // S = Q K^T  (warp: 16 x 64)
        float s[8][4];
        #pragma unroll
        for (int nt = 0; nt < 8; nt++)
            #pragma unroll
            for (int e = 0; e < 4; e++) s[nt][e] = 0.f;

        #pragma unroll
        for (int ks = 0; ks < 4; ks++) {
            unsigned kb[8][2];
            #pragma unroll
            for (int np = 0; np < 4; np++) {
                unsigned r0, r1, r2, r3;
                ldsm4(r0, r1, r2, r3, sK + kboff + np * (16 * KROW) + ks * 32);
                kb[2 * np][0] = r0;     kb[2 * np][1] = r1;
                kb[2 * np + 1][0] = r2; kb[2 * np + 1][1] = r3;
            }
            #pragma unroll
            for (int nt = 0; nt < 8; nt++)
                mma16(s[nt], qa[ks], kb[nt]);
        }

        // scale + causal mask on diagonal tile
        #pragma unroll
        for (int nt = 0; nt < 8; nt++)
            #pragma unroll
            for (int e = 0; e < 4; e++) s[nt][e] *= 0.125f;
        if (j == qt) {
            #pragma unroll
            for (int nt = 0; nt < 8; nt++) {
                int cb = j * 64 + nt * 8 + t * 2;
                if (cb     > r0g)     s[nt][0] = -1e30f;
                if (cb + 1 > r0g)     s[nt][1] = -1e30f;
                if (cb     > r0g + 8) s[nt][2] = -1e30f;
                if (cb + 1 > r0g + 8) s[nt][3] = -1e30f;
            }
        }

        // online softmax (rows g and g+8)
        float t0 = -1e30f, t1 = -1e30f;
        #pragma unroll
        for (int nt = 0; nt < 8; nt++) {
            t0 = fmaxf(t0, fmaxf(s[nt][0], s[nt][1]));
            t1 = fmaxf(t1, fmaxf(s[nt][2], s[nt][3]));
        }
        t0 = fmaxf(t0, __shfl_xor_sync(0xffffffffu, t0, 1));
        t0 = fmaxf(t0, __shfl_xor_sync(0xffffffffu, t0, 2));
        t1 = fmaxf(t1, __shfl_xor_sync(0xffffffffu, t1, 1));
        t1 = fmaxf(t1, __shfl_xor_sync(0xffffffffu, t1, 2));
        float mn0 = fmaxf(m0, t0), mn1 = fmaxf(m1, t1);
        float al0 = __expf(m0 - mn0), al1 = __expf(m1 - mn1);
        float su0 = 0.f, su1 = 0.f;
        #pragma unroll
        for (int nt = 0; nt < 8; nt++) {
            s[nt][0] = __expf(s[nt][0] - mn0); su0 += s[nt][0];
            s[nt][1] = __expf(s[nt][1] - mn0); su0 += s[nt][1];
            s[nt][2] = __expf(s[nt][2] - mn1); su1 += s[nt][2];
            s[nt][3] = __expf(s[nt][3] - mn1); su1 += s[nt][3];
        }
        su0 += __shfl_xor_sync(0xffffffffu, su0, 1);
        su0 += __shfl_xor_sync(0xffffffffu, su0, 2);
        su1 += __shfl_xor_sync(0xffffffffu, su1, 1);
        su1 += __shfl_xor_sync(0xffffffffu, su1, 2);
        l0 = l0 * al0 + su0; l1 = l1 * al1 + su1;
        m0 = mn0; m1 = mn1;
        #pragma unroll
        for (int dt = 0; dt < 8; dt++) {
            o[dt][0] *= al0; o[dt][1] *= al0;
            o[dt][2] *= al1; o[dt][3] *= al1;
        }

        // O += P V   (P: C-frag -> fp16 A-frag in registers)
        #pragma unroll
        for (int ks = 0; ks < 4; ks++) {
            unsigned pa[4];
            pa[0] = packh2(s[2 * ks][0],     s[2 * ks][1]);
            pa[1] = packh2(s[2 * ks][2],     s[2 * ks][3]);
            pa[2] = packh2(s[2 * ks + 1][0], s[2 * ks + 1][1]);
            pa[3] = packh2(s[2 * ks + 1][2], s[2 * ks + 1][3]);
            unsigned vb[8][2];
            #pragma unroll
            for (int np = 0; np < 4; np++) {
                unsigned r0, r1, r2, r3;
                ldsm4t(r0, r1, r2, r3, sV + vboff + ks * (16 * KROW) + np * 32);
                vb[2 * np][0] = r0;     vb[2 * np][1] = r1;
                vb[2 * np + 1][0] = r2; vb[2 * np + 1][1] = r3;
            }
            #pragma unroll
            for (int nt = 0; nt < 8; nt++)
                mma16(o[nt], pa, vb[nt]);
        }

        __syncthreads();   // protect stage reuse before next fill
    }

    const float i0 = 1.0f / l0, i1 = 1.0f / l1;
    #pragma unroll
    for (int dt = 0; dt < 8; dt++) {
        int col = dt * 8 + t * 2;
        size_t off0 = obase + (size_t)r0g * EMB + col;
        size_t off1 = obase + (size_t)(r0g + 8) * EMB + col;
        *(__half2*)(O + off0) = __floats2half2_rn(o[dt][0] * i0, o[dt][1] * i0);
        *(__half2*)(O + off1) = __floats2half2_rn(o[dt][2] * i1, o[dt][3] * i1);
    }
}

// -------------------- launch --------------------
extern "C" void kernel_launch(void* const* d_in, const int* in_sizes, int n_in,
                              void* d_out, int out_size)
{
    const float* x     = (const float*)d_in[0];
    const float* w_q   = (const float*)d_in[1];
    const float* w_k   = (const float*)d_in[2];
    const float* w_v   = (const float*)d_in[3];
    const float* w_o   = (const float*)d_in[4];
    const float* b_o   = (const float*)d_in[5];
    const float* ln1s  = (const float*)d_in[6];
    const float* ln1b  = (const float*)d_in[7];
    const float* ln2s  = (const float*)d_in[8];
    const float* ln2b  = (const float*)d_in[9];
    const float* w_ff1 = (const float*)d_in[10];
    const float* b_ff1 = (const float*)d_in[11];
    const float* w_ff2 = (const float*)d_in[12];
    const float* b_ff2 = (const float*)d_in[13];
    float* out = (float*)d_out;

    void *p;
    cudaGetSymbolAddress(&p, g_ln16);   __half* ln16   = (__half*)p;
    cudaGetSymbolAddress(&p, g_qkv16);  __half* qkv16  = (__half*)p;
    cudaGetSymbolAddress(&p, g_ctx16);  __half* ctx16  = (__half*)p;
    cudaGetSymbolAddress(&p, g_ff16);   __half* ff16   = (__half*)p;
    cudaGetSymbolAddress(&p, g_x1);     float*  x1     = (float*)p;
    cudaGetSymbolAddress(&p, g_wqkv16); __half* wqkv16 = (__half*)p;
    cudaGetSymbolAddress(&p, g_wo16);   __half* wo16   = (__half*)p;
    cudaGetSymbolAddress(&p, g_wf116);  __half* wf116  = (__half*)p;
    cudaGetSymbolAddress(&p, g_wf216);  __half* wf216  = (__half*)p;

    cudaFuncSetAttribute((const void*)gemm16<EP_H>,
                         cudaFuncAttributeMaxDynamicSharedMemorySize, GEMM_SMEM);
    cudaFuncSetAttribute((const void*)gemm16<EP_GELU_H>,
                         cudaFuncAttributeMaxDynamicSharedMemorySize, GEMM_SMEM);
    cudaFuncSetAttribute((const void*)gemm16<EP_RES_F>,
                         cudaFuncAttributeMaxDynamicSharedMemorySize, GEMM_SMEM);
    cudaFuncSetAttribute((const void*)attn16,
                         cudaFuncAttributeMaxDynamicSharedMemorySize, ATT_SMEM);

    const int t4_1M = EMB * EMB / 4;
    const int t4_4M = EMB * FFDIM / 4;
    round_h<<<(t4_1M + 255) / 256, 256>>>(w_q, wqkv16,           EMB, 3 * EMB, t4_1M);
    round_h<<<(t4_1M + 255) / 256, 256>>>(w_k, wqkv16 + EMB,     EMB, 3 * EMB, t4_1M);
    round_h<<<(t4_1M + 255) / 256, 256>>>(w_v, wqkv16 + 2 * EMB, EMB, 3 * EMB, t4_1M);
    round_h<<<(t4_1M + 255) / 256, 256>>>(w_o,   wo16,  EMB,   EMB,   t4_1M);
    round_h<<<(t4_4M + 255) / 256, 256>>>(w_ff1, wf116, FFDIM, FFDIM, t4_4M);
    round_h<<<(t4_4M + 255) / 256, 256>>>(w_ff2, wf216, EMB,   EMB,   t4_4M);

    // h = LN1(x)
    ln16_kernel<<<NROWS, 256>>>(x, ln1s, ln1b, ln16);
    // qkv = h @ [Wq|Wk|Wv]
    gemm16<EP_H><<<dim3(3 * EMB / BN, NROWS / BM), 128, GEMM_SMEM>>>(
        ln16, wqkv16, nullptr, nullptr, qkv16, NROWS, 3 * EMB, EMB);
    // ctx = causal attention
    attn16<<<dim3(SEQ / 64, BATCH * NHEADS), 128, ATT_SMEM>>>(
        qkv16, qkv16 + EMB, qkv16 + 2 * EMB, ctx16, 3 * EMB);
    // x1 = x + ctx @ w_o + b_o
    gemm16<EP_RES_F><<<dim3(EMB / BN, NROWS / BM), 128, GEMM_SMEM>>>(
        ctx16, wo16, b_o, x, x1, NROWS, EMB, EMB);
    // h = LN2(x1)
    ln16_kernel<<<NROWS, 256>>>(x1, ln2s, ln2b, ln16);
    // ff = gelu(h @ w_ff1 + b_ff1)
    gemm16<EP_GELU_H><<<dim3(FFDIM / BN, NROWS / BM), 128, GEMM_SMEM>>>(
        ln16, wf116, b_ff1, nullptr, ff16, NROWS, FFDIM, EMB);
    // out = x1 + ff @ w_ff2 + b_ff2
    gemm16<EP_RES_F><<<dim3(EMB / BN, NROWS / BM), 128, GEMM_SMEM>>>(
        ff16, wf216, b_ff2, x1, out, NROWS, EMB, FFDIM);
}

// round 7
// speedup vs baseline: 2.3302x; 1.0041x over previous
#include <cuda_runtime.h>
#include <cuda_fp16.h>
#include <cstdint>
#include <math.h>

#define EMB 1024
#define SEQ 2048
#define BATCH 2
#define NROWS 4096          // BATCH*SEQ
#define FFDIM 4096
#define NHEADS 16
#define HDIM 64

// -------------------- scratch (no allocation allowed) --------------------
__device__ unsigned short g_ln16 [NROWS * EMB];
__device__ unsigned short g_qkv16[(size_t)NROWS * 3 * EMB];
__device__ unsigned short g_ctx16[NROWS * EMB];
__device__ unsigned short g_ff16 [(size_t)NROWS * FFDIM];
__device__ float          g_x1   [NROWS * EMB];
__device__ unsigned short g_wqkv16[(size_t)EMB * 3 * EMB];
__device__ unsigned short g_wo16  [(size_t)EMB * EMB];
__device__ unsigned short g_wf116 [(size_t)EMB * FFDIM];
__device__ unsigned short g_wf216 [(size_t)FFDIM * EMB];

// -------------------- helpers --------------------
__device__ __forceinline__ float gelu_f(float v) {
    float u = v + 0.044715f * v * v * v;
    return 0.5f * v * (1.0f + tanhf(0.7978845608028654f * u));
}

__device__ __forceinline__ uint32_t smem_u32(const void* p) {
    uint32_t a;
    asm("{ .reg .u64 t; cvta.to.shared.u64 t, %1; cvt.u32.u64 %0, t; }" : "=r"(a) : "l"(p));
    return a;
}

__device__ __forceinline__ unsigned packh2(float lo, float hi) {
    unsigned r;
    asm("cvt.rn.f16x2.f32 %0, %1, %2;" : "=r"(r) : "f"(hi), "f"(lo));
    return r;
}

__device__ __forceinline__ void mma16(float* c, const unsigned* a, const unsigned* b) {
    asm volatile(
        "mma.sync.aligned.m16n8k16.row.col.f32.f16.f16.f32 "
        "{%0,%1,%2,%3}, {%4,%5,%6,%7}, {%8,%9}, {%0,%1,%2,%3};\n"
        : "+f"(c[0]), "+f"(c[1]), "+f"(c[2]), "+f"(c[3])
        : "r"(a[0]), "r"(a[1]), "r"(a[2]), "r"(a[3]),
          "r"(b[0]), "r"(b[1]));
}

__device__ __forceinline__ void ldsm4(unsigned& r0, unsigned& r1, unsigned& r2, unsigned& r3,
                                      uint32_t addr) {
    asm volatile("ldmatrix.sync.aligned.m8n8.x4.shared.b16 {%0,%1,%2,%3}, [%4];"
                 : "=r"(r0), "=r"(r1), "=r"(r2), "=r"(r3) : "r"(addr));
}
__device__ __forceinline__ void ldsm4t(unsigned& r0, unsigned& r1, unsigned& r2, unsigned& r3,
                                       uint32_t addr) {
    asm volatile("ldmatrix.sync.aligned.m8n8.x4.trans.shared.b16 {%0,%1,%2,%3}, [%4];"
                 : "=r"(r0), "=r"(r1), "=r"(r2), "=r"(r3) : "r"(addr));
}

__device__ __forceinline__ void cpa16(uint32_t dst, const void* src) {
    asm volatile("cp.async.cg.shared.global [%0], [%1], 16;" :: "r"(dst), "l"(src));
}
#define CPA_COMMIT() asm volatile("cp.async.commit_group;" ::: "memory")
template<int N> __device__ __forceinline__ void cpa_wait() {
    asm volatile("cp.async.wait_group %0;" :: "n"(N) : "memory");
}

// -------------------- fused f32 -> f16 weight conversion -------------------
// regions (in float4 units): wq,wk,wv (262144 each, strided into wqkv),
// wo (262144), wf1 (1048576), wf2 (1048576). boundaries are block-aligned.
#define R1M (EMB * EMB / 4)
#define R4M (EMB * FFDIM / 4)
__global__ void __launch_bounds__(256)
round_all(const float* __restrict__ wq, const float* __restrict__ wk,
          const float* __restrict__ wv, const float* __restrict__ wo,
          const float* __restrict__ wf1, const float* __restrict__ wf2,
          __half* __restrict__ wqkv, __half* __restrict__ wo16,
          __half* __restrict__ wf116, __half* __restrict__ wf216)
{
    int idx = blockIdx.x * 256 + threadIdx.x;
    const float* src; __half* dst; int cols, ldo;
    if (idx < R1M)            { src = wq;  dst = wqkv;           cols = EMB;   ldo = 3 * EMB; }
    else if (idx < 2 * R1M)   { idx -= R1M;     src = wk;  dst = wqkv + EMB;     cols = EMB;   ldo = 3 * EMB; }
    else if (idx < 3 * R1M)   { idx -= 2 * R1M; src = wv;  dst = wqkv + 2 * EMB; cols = EMB;   ldo = 3 * EMB; }
    else if (idx < 4 * R1M)   { idx -= 3 * R1M; src = wo;  dst = wo16;           cols = EMB;   ldo = EMB; }
    else if (idx < 4 * R1M + R4M) { idx -= 4 * R1M; src = wf1; dst = wf116;      cols = FFDIM; ldo = FFDIM; }
    else                      { idx -= 4 * R1M + R4M; src = wf2; dst = wf216;    cols = EMB;   ldo = EMB; }
    int c4 = cols >> 2;
    int r = idx / c4, c = (idx - r * c4) * 4;
    float4 v = *(const float4*)(src + (size_t)r * cols + c);
    __half2 h0 = __floats2half2_rn(v.x, v.y);
    __half2 h1 = __floats2half2_rn(v.z, v.w);
    __half2* o = (__half2*)(dst + (size_t)r * ldo + c);
    o[0] = h0; o[1] = h1;
}
#define ROUND_ALL_BLOCKS (4 * R1M / 256 + 2 * R4M / 256)

// -------------------- layernorm (fp16 output) -------------------------------
__global__ void __launch_bounds__(256)
ln16_kernel(const float* __restrict__ x, const float* __restrict__ sc,
            const float* __restrict__ sh, __half* __restrict__ out)
{
    __shared__ float red[8];
    __shared__ float stats[2];
    const int row = blockIdx.x, tid = threadIdx.x, lane = tid & 31, warp = tid >> 5;
    const float* xr = x + (size_t)row * EMB;
    float4 v = *(const float4*)(xr + tid * 4);

    float s = v.x + v.y + v.z + v.w;
    #pragma unroll
    for (int o = 16; o > 0; o >>= 1) s += __shfl_xor_sync(0xffffffffu, s, o);
    if (lane == 0) red[warp] = s;
    __syncthreads();
    if (tid == 0) {
        float t = 0.f;
        #pragma unroll
        for (int i = 0; i < 8; i++) t += red[i];
        stats[0] = t * (1.0f / EMB);
    }
    __syncthreads();
    const float mean = stats[0];
    float dx = v.x - mean, dy = v.y - mean, dz = v.z - mean, dw = v.w - mean;
    float ss = dx * dx + dy * dy + dz * dz + dw * dw;
    #pragma unroll
    for (int o = 16; o > 0; o >>= 1) ss += __shfl_xor_sync(0xffffffffu, ss, o);
    if (lane == 0) red[warp] = ss;
    __syncthreads();
    if (tid == 0) {
        float t = 0.f;
        #pragma unroll
        for (int i = 0; i < 8; i++) t += red[i];
        stats[1] = rsqrtf(t * (1.0f / EMB) + 1e-5f);
    }
    __syncthreads();
    const float rstd = stats[1];
    float4 scv = *(const float4*)(sc + tid * 4);
    float4 shv = *(const float4*)(sh + tid * 4);
    __half2 h0 = __floats2half2_rn(scv.x * dx * rstd + shv.x, scv.y * dy * rstd + shv.y);
    __half2 h1 = __floats2half2_rn(scv.z * dz * rstd + shv.z, scv.w * dw * rstd + shv.w);
    __half2* o = (__half2*)(out + (size_t)row * EMB + tid * 4);
    o[0] = h0; o[1] = h1;
}

// -------------------- shared GEMM constants --------------------
#define BK 64
#define A_ROW_B 144           // (64+8) halves * 2B
#define B_ROW_B 272           // (128+8) halves * 2B

enum { EP_H = 0, EP_GELU_H = 1, EP_RES_F = 2 };

// ==================== GEMM small: 128x128, 128 thr, 2 CTA/SM ===============
#define BM 128
#define BN 128
#define ASTG (BM * A_ROW_B)
#define BSTG (BK * B_ROW_B)
#define STGB (ASTG + BSTG)
#define GEMM_SMEM (3 * STGB)

__device__ __forceinline__ void fill_stage16(uint32_t sA, uint32_t sB,
                                             const __half* __restrict__ A,
                                             const __half* __restrict__ B,
                                             int bm, int bn, int N, int K, int kc, int tid)
{
    #pragma unroll
    for (int i = 0; i < 8; i++) {
        int e = tid + i * 128;
        int row = e >> 3, seg = e & 7;
        cpa16(sA + row * A_ROW_B + seg * 16,
              A + (size_t)(bm + row) * K + kc * BK + seg * 8);
    }
    #pragma unroll
    for (int i = 0; i < 8; i++) {
        int e = tid + i * 128;
        int row = e >> 4, seg = e & 15;
        cpa16(sB + row * B_ROW_B + seg * 16,
              B + (size_t)(kc * BK + row) * N + bn + seg * 8);
    }
}

template<int EPI>
__global__ void __launch_bounds__(128, 2)
gemm16(const __half* __restrict__ A, const __half* __restrict__ B,
       const float* __restrict__ bias, const float* __restrict__ R,
       void* __restrict__ Cv, int M, int N, int K)
{
    extern __shared__ char smem[];
    const uint32_t sbase = smem_u32(smem);

    const int tid = threadIdx.x, lane = tid & 31, warp = tid >> 5;
    const int bm = blockIdx.y * BM, bn = blockIdx.x * BN;
    const int wm = (warp & 1) * 64, wn = (warp >> 1) * 64;
    const int g = lane >> 2, t = lane & 3;
    const int NK = K / BK;

    float c[4][8][4];
    #pragma unroll
    for (int mt = 0; mt < 4; mt++)
        #pragma unroll
        for (int nt = 0; nt < 8; nt++)
            #pragma unroll
            for (int e = 0; e < 4; e++) c[mt][nt][e] = 0.f;

    fill_stage16(sbase,        sbase + ASTG,        A, B, bm, bn, N, K, 0, tid);
    CPA_COMMIT();
    fill_stage16(sbase + STGB, sbase + STGB + ASTG, A, B, bm, bn, N, K, 1, tid);
    CPA_COMMIT();

    const uint32_t laoff = (wm + (lane & 15)) * A_ROW_B + (lane >> 4) * 16;
    const uint32_t lboff = (lane & 15) * B_ROW_B + (lane >> 4) * 16 + wn * 2;

    int stg = 0;
    for (int kt = 0; kt < NK; kt++) {
        if (kt == NK - 1) cpa_wait<0>(); else cpa_wait<1>();
        __syncthreads();

        if (kt + 2 < NK) {
            int fs = kt + 2; fs -= (fs / 3) * 3;
            fill_stage16(sbase + fs * STGB, sbase + fs * STGB + ASTG,
                         A, B, bm, bn, N, K, kt + 2, tid);
            CPA_COMMIT();
        }

        const uint32_t sA = sbase + stg * STGB;
        const uint32_t sB = sA + ASTG;
        const uint32_t la = sA + laoff;
        const uint32_t lb = sB + lboff;

        #pragma unroll
        for (int ks = 0; ks < 4; ks++) {
            unsigned a[4][4], b[8][2];
            #pragma unroll
            for (int mt = 0; mt < 4; mt++)
                ldsm4(a[mt][0], a[mt][1], a[mt][2], a[mt][3],
                      la + mt * (16 * A_ROW_B) + ks * 32);
            #pragma unroll
            for (int np = 0; np < 4; np++) {
                unsigned r0, r1, r2, r3;
                ldsm4t(r0, r1, r2, r3, lb + ks * (16 * B_ROW_B) + np * 32);
                b[2 * np][0] = r0;     b[2 * np][1] = r1;
                b[2 * np + 1][0] = r2; b[2 * np + 1][1] = r3;
            }
            #pragma unroll
            for (int mt = 0; mt < 4; mt++)
                #pragma unroll
                for (int nt = 0; nt < 8; nt++)
                    mma16(c[mt][nt], a[mt], b[nt]);
        }

        stg++; if (stg == 3) stg = 0;
    }

    #pragma unroll
    for (int mt = 0; mt < 4; mt++) {
        #pragma unroll
        for (int nt = 0; nt < 8; nt++) {
            const int row0 = bm + wm + mt * 16 + g;
            const int col  = bn + wn + nt * 8 + t * 2;
            #pragma unroll
            for (int h = 0; h < 2; h++) {
                const int row = row0 + h * 8;
                float v0 = c[mt][nt][2 * h], v1 = c[mt][nt][2 * h + 1];
                const size_t off = (size_t)row * N + col;
                if (EPI == EP_H) {
                    *(__half2*)((__half*)Cv + off) = __floats2half2_rn(v0, v1);
                } else if (EPI == EP_GELU_H) {
                    float2 bb = *(const float2*)(bias + col);
                    *(__half2*)((__half*)Cv + off) =
                        __floats2half2_rn(gelu_f(v0 + bb.x), gelu_f(v1 + bb.y));
                } else {
                    float2 bb = *(const float2*)(bias + col);
                    float2 rr = *(const float2*)(R + off);
                    *(float2*)((float*)Cv + off) =
                        make_float2(v0 + bb.x + rr.x, v1 + bb.y + rr.y);
                }
            }
        }
    }
}

// ==================== GEMM big: 256x128, 256 thr, 1 CTA/SM =================
#define BM2 256
#define ASTG2 (BM2 * A_ROW_B)        // 36864
#define STGB2 (ASTG2 + BSTG)         // 54272
#define GEMM2_SMEM (3 * STGB2)       // 162816

__device__ __forceinline__ void fill_stage16b(uint32_t sA, uint32_t sB,
                                              const __half* __restrict__ A,
                                              const __half* __restrict__ B,
                                              int bm, int bn, int N, int K, int kc, int tid)
{
    #pragma unroll
    for (int i = 0; i < 8; i++) {
        int e = tid + i * 256;
        int row = e >> 3, seg = e & 7;
        cpa16(sA + row * A_ROW_B + seg * 16,
              A + (size_t)(bm + row) * K + kc * BK + seg * 8);
    }
    #pragma unroll
    for (int i = 0; i < 4; i++) {
        int e = tid + i * 256;
        int row = e >> 4, seg = e & 15;
        cpa16(sB + row * B_ROW_B + seg * 16,
              B + (size_t)(kc * BK + row) * N + bn + seg * 8);
    }
}

template<int EPI>
__global__ void __launch_bounds__(256, 1)
gemm16b(const __half* __restrict__ A, const __half* __restrict__ B,
        const float* __restrict__ bias, const float* __restrict__ R,
        void* __restrict__ Cv, int M, int N, int K)
{
    extern __shared__ char smem[];
    const uint32_t sbase = smem_u32(smem);

    const int tid = threadIdx.x, lane = tid & 31, warp = tid >> 5;
    const int bm = blockIdx.y * BM2, bn = blockIdx.x * BN;
    const int wm = (warp & 3) * 64, wn = (warp >> 2) * 64;
    const int g = lane >> 2, t = lane & 3;
    const int NK = K / BK;

    float c[4][8][4];
    #pragma unroll
    for (int mt = 0; mt < 4; mt++)
        #pragma unroll
        for (int nt = 0; nt < 8; nt++)
            #pragma unroll
            for (int e = 0; e < 4; e++) c[mt][nt][e] = 0.f;

    fill_stage16b(sbase,         sbase + ASTG2,         A, B, bm, bn, N, K, 0, tid);
    CPA_COMMIT();
    fill_stage16b(sbase + STGB2, sbase + STGB2 + ASTG2, A, B, bm, bn, N, K, 1, tid);
    CPA_COMMIT();

    const uint32_t laoff = (wm + (lane & 15)) * A_ROW_B + (lane >> 4) * 16;
    const uint32_t lboff = (lane & 15) * B_ROW_B + (lane >> 4) * 16 + wn * 2;

    int stg = 0;
    for (int kt = 0; kt < NK; kt++) {
        if (kt == NK - 1) cpa_wait<0>(); else cpa_wait<1>();
        __syncthreads();

        if (kt + 2 < NK) {
            int fs = kt + 2; fs -= (fs / 3) * 3;
            fill_stage16b(sbase + fs * STGB2, sbase + fs * STGB2 + ASTG2,
                          A, B, bm, bn, N, K, kt + 2, tid);
            CPA_COMMIT();
        }

        const uint32_t sA = sbase + stg * STGB2;
        const uint32_t sB = sA + ASTG2;
        const uint32_t la = sA + laoff;
        const uint32_t lb = sB + lboff;

        #pragma unroll
        for (int ks = 0; ks < 4; ks++) {
            unsigned a[4][4], b[8][2];
            #pragma unroll
            for (int mt = 0; mt < 4; mt++)
                ldsm4(a[mt][0], a[mt][1], a[mt][2], a[mt][3],
                      la + mt * (16 * A_ROW_B) + ks * 32);
            #pragma unroll
            for (int np = 0; np < 4; np++) {
                unsigned r0, r1, r2, r3;
                ldsm4t(r0, r1, r2, r3, lb + ks * (16 * B_ROW_B) + np * 32);
                b[2 * np][0] = r0;     b[2 * np][1] = r1;
                b[2 * np + 1][0] = r2; b[2 * np + 1][1] = r3;
            }
            #pragma unroll
            for (int mt = 0; mt < 4; mt++)
                #pragma unroll
                for (int nt = 0; nt < 8; nt++)
                    mma16(c[mt][nt], a[mt], b[nt]);
        }

        stg++; if (stg == 3) stg = 0;
    }

    #pragma unroll
    for (int mt = 0; mt < 4; mt++) {
        #pragma unroll
        for (int nt = 0; nt < 8; nt++) {
            const int row0 = bm + wm + mt * 16 + g;
            const int col  = bn + wn + nt * 8 + t * 2;
            #pragma unroll
            for (int h = 0; h < 2; h++) {
                const int row = row0 + h * 8;
                float v0 = c[mt][nt][2 * h], v1 = c[mt][nt][2 * h + 1];
                const size_t off = (size_t)row * N + col;
                if (EPI == EP_H) {
                    *(__half2*)((__half*)Cv + off) = __floats2half2_rn(v0, v1);
                } else if (EPI == EP_GELU_H) {
                    float2 bb = *(const float2*)(bias + col);
                    *(__half2*)((__half*)Cv + off) =
                        __floats2half2_rn(gelu_f(v0 + bb.x), gelu_f(v1 + bb.y));
                } else {
                    float2 bb = *(const float2*)(bias + col);
                    float2 rr = *(const float2*)(R + off);
                    *(float2*)((float*)Cv + off) =
                        make_float2(v0 + bb.x + rr.x, v1 + bb.y + rr.y);
                }
            }
        }
    }
}

// -------------------- fp16 causal flash attention (Br=Bc=64, d=64) ---------
#define KROW 144
#define KVTILE (64 * KROW)
#define ATT_SMEM (KVTILE + 2 * 2 * KVTILE)

__global__ void __launch_bounds__(128, 2)
attn16(const __half* __restrict__ Qg, const __half* __restrict__ Kg,
       const __half* __restrict__ Vg, __half* __restrict__ O, int ldq)
{
    extern __shared__ char smem[];
    const uint32_t sbase = smem_u32(smem);
    const uint32_t sQ = sbase;

    const int tid = threadIdx.x, lane = tid & 31, warp = tid >> 5;
    const int g = lane >> 2, t = lane & 3;

    const int qt = blockIdx.x;
    const int bh = blockIdx.y;
    const int b = bh >> 4, h = bh & 15;
    const size_t qbase = (size_t)b * SEQ * ldq + (size_t)h * HDIM;
    const size_t obase = (size_t)b * SEQ * EMB + (size_t)h * HDIM;

    auto fill_kv = [&](int s, int j) {
        const uint32_t sK = sbase + KVTILE + s * (2 * KVTILE);
        const uint32_t sV = sK + KVTILE;
        #pragma unroll
        for (int i = 0; i < 4; i++) {
            int e = tid + i * 128;
            int row = e >> 3, seg = e & 7;
            size_t go = qbase + (size_t)(j * 64 + row) * ldq + seg * 8;
            cpa16(sK + row * KROW + seg * 16, Kg + go);
            cpa16(sV + row * KROW + seg * 16, Vg + go);
        }
    };

    fill_kv(0, 0);
    CPA_COMMIT();

    #pragma unroll
    for (int i = 0; i < 4; i++) {
        int e = tid + i * 128;
        int row = e >> 3, seg = e & 7;
        *(uint4*)(smem + row * KROW + seg * 16) =
            *(const uint4*)(Qg + qbase + (size_t)(qt * 64 + row) * ldq + seg * 8);
    }
    __syncthreads();

    unsigned qa[4][4];
    {
        const uint32_t la = sQ + (warp * 16 + (lane & 15)) * KROW + (lane >> 4) * 16;
        #pragma unroll
        for (int ks = 0; ks < 4; ks++)
            ldsm4(qa[ks][0], qa[ks][1], qa[ks][2], qa[ks][3], la + ks * 32);
    }

    const uint32_t kboff = ((lane & 7) + ((lane >> 4) << 3)) * KROW + ((lane >> 3) & 1) * 16;
    const uint32_t vboff = (lane & 15) * KROW + (lane >> 4) * 16;

    float m0 = -1e30f, m1 = -1e30f, l0 = 0.f, l1 = 0.f;
    float o[8][4];
    #pragma unroll
    for (int dt = 0; dt < 8; dt++)
        #pragma unroll
        for (int e = 0; e < 4; e++) o[dt][e] = 0.f;

    const int r0g = qt * 64 + warp * 16 + g;

    for (int j = 0; j <= qt; j++) {
        if (j < qt) { fill_kv((j + 1) & 1, j + 1); CPA_COMMIT(); }
        if (j < qt) cpa_wait<1>(); else cpa_wait<0>();
        __syncthreads();

        const uint32_t sK = sbase + KVTILE + (j & 1) * (2 * KVTILE);
        const uint32_t sV = sK + KVTILE;

        float s[8][4];
        #pragma unroll
        for (int nt = 0; nt < 8; nt++)
            #pragma unroll
            for (int e = 0; e < 4; e++) s[nt][e] = 0.f;

        #pragma unroll
        for (int ks = 0; ks < 4; ks++) {
            unsigned kb[8][2];
            #pragma unroll
            for (int np = 0; np < 4; np++) {
                unsigned r0, r1, r2, r3;
                ldsm4(r0, r1, r2, r3, sK + kboff + np * (16 * KROW) + ks * 32);
                kb[2 * np][0] = r0;     kb[2 * np][1] = r1;
                kb[2 * np + 1][0] = r2; kb[2 * np + 1][1] = r3;
            }
            #pragma unroll
            for (int nt = 0; nt < 8; nt++)
                mma16(s[nt], qa[ks], kb[nt]);
        }

        #pragma unroll
        for (int nt = 0; nt < 8; nt++)
            #pragma unroll
            for (int e = 0; e < 4; e++) s[nt][e] *= 0.125f;
        if (j == qt) {
            #pragma unroll
            for (int nt = 0; nt < 8; nt++) {
                int cb = j * 64 + nt * 8 + t * 2;
                if (cb     > r0g)     s[nt][0] = -1e30f;
                if (cb + 1 > r0g)     s[nt][1] = -1e30f;
                if (cb     > r0g + 8) s[nt][2] = -1e30f;
                if (cb + 1 > r0g + 8) s[nt][3] = -1e30f;
            }
        }

        float t0 = -1e30f, t1 = -1e30f;
        #pragma unroll
        for (int nt = 0; nt < 8; nt++) {
            t0 = fmaxf(t0, fmaxf(s[nt][0], s[nt][1]));
            t1 = fmaxf(t1, fmaxf(s[nt][2], s[nt][3]));
        }
        t0 = fmaxf(t0, __shfl_xor_sync(0xffffffffu, t0, 1));
        t0 = fmaxf(t0, __shfl_xor_sync(0xffffffffu, t0, 2));
        t1 = fmaxf(t1, __shfl_xor_sync(0xffffffffu, t1, 1));
        t1 = fmaxf(t1, __shfl_xor_sync(0xffffffffu, t1, 2));
        float mn0 = fmaxf(m0, t0), mn1 = fmaxf(m1, t1);
        float al0 = __expf(m0 - mn0), al1 = __expf(m1 - mn1);
        float su0 = 0.f, su1 = 0.f;
        #pragma unroll
        for (int nt = 0; nt < 8; nt++) {
            s[nt][0] = __expf(s[nt][0] - mn0); su0 += s[nt][0];
            s[nt][1] = __expf(s[nt][1] - mn0); su0 += s[nt][1];
            s[nt][2] = __expf(s[nt][2] - mn1); su1 += s[nt][2];
            s[nt][3] = __expf(s[nt][3] - mn1); su1 += s[nt][3];
        }
        su0 += __shfl_xor_sync(0xffffffffu, su0, 1);
        su0 += __shfl_xor_sync(0xffffffffu, su0, 2);
        su1 += __shfl_xor_sync(0xffffffffu, su1, 1);
        su1 += __shfl_xor_sync(0xffffffffu, su1, 2);
        l0 = l0 * al0 + su0; l1 = l1 * al1 + su1;
        m0 = mn0; m1 = mn1;
        #pragma unroll
        for (int dt = 0; dt < 8; dt++) {
            o[dt][0] *= al0; o[dt][1] *= al0;
            o[dt][2] *= al1; o[dt][3] *= al1;
        }

        #pragma unroll
        for (int ks = 0; ks < 4; ks++) {
            unsigned pa[4];
            pa[0] = packh2(s[2 * ks][0],     s[2 * ks][1]);
            pa[1] = packh2(s[2 * ks][2],     s[2 * ks][3]);
            pa[2] = packh2(s[2 * ks + 1][0], s[2 * ks + 1][1]);
            pa[3] = packh2(s[2 * ks + 1][2], s[2 * ks + 1][3]);
            unsigned vb[8][2];
            #pragma unroll
            for (int np = 0; np < 4; np++) {
                unsigned r0, r1, r2, r3;
                ldsm4t(r0, r1, r2, r3, sV + vboff + ks * (16 * KROW) + np * 32);
                vb[2 * np][0] = r0;     vb[2 * np][1] = r1;
                vb[2 * np + 1][0] = r2; vb[2 * np + 1][1] = r3;
            }
            #pragma unroll
            for (int nt = 0; nt < 8; nt++)
                mma16(o[nt], pa, vb[nt]);
        }

        __syncthreads();
    }

    const float i0 = 1.0f / l0, i1 = 1.0f / l1;
    #pragma unroll
    for (int dt = 0; dt < 8; dt++) {
        int col = dt * 8 + t * 2;
        size_t off0 = obase + (size_t)r0g * EMB + col;
        size_t off1 = obase + (size_t)(r0g + 8) * EMB + col;
        *(__half2*)(O + off0) = __floats2half2_rn(o[dt][0] * i0, o[dt][1] * i0);
        *(__half2*)(O + off1) = __floats2half2_rn(o[dt][2] * i1, o[dt][3] * i1);
    }
}

// -------------------- launch --------------------
extern "C" void kernel_launch(void* const* d_in, const int* in_sizes, int n_in,
                              void* d_out, int out_size)
{
    const float* x     = (const float*)d_in[0];
    const float* w_q   = (const float*)d_in[1];
    const float* w_k   = (const float*)d_in[2];
    const float* w_v   = (const float*)d_in[3];
    const float* w_o   = (const float*)d_in[4];
    const float* b_o   = (const float*)d_in[5];
    const float* ln1s  = (const float*)d_in[6];
    const float* ln1b  = (const float*)d_in[7];
    const float* ln2s  = (const float*)d_in[8];
    const float* ln2b  = (const float*)d_in[9];
    const float* w_ff1 = (const float*)d_in[10];
    const float* b_ff1 = (const float*)d_in[11];
    const float* w_ff2 = (const float*)d_in[12];
    const float* b_ff2 = (const float*)d_in[13];
    float* out = (float*)d_out;

    void *p;
    cudaGetSymbolAddress(&p, g_ln16);   __half* ln16   = (__half*)p;
    cudaGetSymbolAddress(&p, g_qkv16);  __half* qkv16  = (__half*)p;
    cudaGetSymbolAddress(&p, g_ctx16);  __half* ctx16  = (__half*)p;
    cudaGetSymbolAddress(&p, g_ff16);   __half* ff16   = (__half*)p;
    cudaGetSymbolAddress(&p, g_x1);     float*  x1     = (float*)p;
    cudaGetSymbolAddress(&p, g_wqkv16); __half* wqkv16 = (__half*)p;
    cudaGetSymbolAddress(&p, g_wo16);   __half* wo16   = (__half*)p;
    cudaGetSymbolAddress(&p, g_wf116);  __half* wf116  = (__half*)p;
    cudaGetSymbolAddress(&p, g_wf216);  __half* wf216  = (__half*)p;

    cudaFuncSetAttribute((const void*)gemm16<EP_RES_F>,
                         cudaFuncAttributeMaxDynamicSharedMemorySize, GEMM_SMEM);
    cudaFuncSetAttribute((const void*)gemm16b<EP_H>,
                         cudaFuncAttributeMaxDynamicSharedMemorySize, GEMM2_SMEM);
    cudaFuncSetAttribute((const void*)gemm16b<EP_GELU_H>,
                         cudaFuncAttributeMaxDynamicSharedMemorySize, GEMM2_SMEM);
    cudaFuncSetAttribute((const void*)attn16,
                         cudaFuncAttributeMaxDynamicSharedMemorySize, ATT_SMEM);

    // weights -> fp16, single launch
    round_all<<<ROUND_ALL_BLOCKS, 256>>>(w_q, w_k, w_v, w_o, w_ff1, w_ff2,
                                         wqkv16, wo16, wf116, wf216);

    // h = LN1(x)
    ln16_kernel<<<NROWS, 256>>>(x, ln1s, ln1b, ln16);
    // qkv = h @ [Wq|Wk|Wv]   (big tile: grid 24 x 16)
    gemm16b<EP_H><<<dim3(3 * EMB / BN, NROWS / BM2), 256, GEMM2_SMEM>>>(
        ln16, wqkv16, nullptr, nullptr, qkv16, NROWS, 3 * EMB, EMB);
    // ctx = causal attention
    attn16<<<dim3(SEQ / 64, BATCH * NHEADS), 128, ATT_SMEM>>>(
        qkv16, qkv16 + EMB, qkv16 + 2 * EMB, ctx16, 3 * EMB);
    // x1 = x + ctx @ w_o + b_o    (small tile: grid 8 x 32 = 256 blocks)
    gemm16<EP_RES_F><<<dim3(EMB / BN, NROWS / BM), 128, GEMM_SMEM>>>(
        ctx16, wo16, b_o, x, x1, NROWS, EMB, EMB);
    // h = LN2(x1)
    ln16_kernel<<<NROWS, 256>>>(x1, ln2s, ln2b, ln16);
    // ff = gelu(h @ w_ff1 + b_ff1)   (big tile: grid 32 x 16)
    gemm16b<EP_GELU_H><<<dim3(FFDIM / BN, NROWS / BM2), 256, GEMM2_SMEM>>>(
        ln16, wf116, b_ff1, nullptr, ff16, NROWS, FFDIM, EMB);
    // out = x1 + ff @ w_ff2 + b_ff2  (small tile)
    gemm16<EP_RES_F><<<dim3(EMB / BN, NROWS / BM), 128, GEMM_SMEM>>>(
        ff16, wf216, b_ff2, x1, out, NROWS, EMB, FFDIM);
}

// round 8
// speedup vs baseline: 2.3684x; 1.0164x over previous
#include <cuda_runtime.h>
#include <cuda_fp16.h>
#include <cstdint>
#include <math.h>

#define EMB 1024
#define SEQ 2048
#define BATCH 2
#define NROWS 4096          // BATCH*SEQ
#define FFDIM 4096
#define NHEADS 16
#define HDIM 64

// -------------------- scratch (no allocation allowed) --------------------
__device__ unsigned short g_ln16 [NROWS * EMB];
__device__ unsigned short g_qkv16[(size_t)NROWS * 3 * EMB];
__device__ unsigned short g_ctx16[NROWS * EMB];
__device__ unsigned short g_ff16 [(size_t)NROWS * FFDIM];
__device__ float          g_x1   [NROWS * EMB];
__device__ unsigned short g_wqkv16[(size_t)EMB * 3 * EMB];
__device__ unsigned short g_wo16  [(size_t)EMB * EMB];
__device__ unsigned short g_wf116 [(size_t)EMB * FFDIM];
__device__ unsigned short g_wf216 [(size_t)FFDIM * EMB];

// -------------------- helpers --------------------
__device__ __forceinline__ float gelu_f(float v) {
    float u = v + 0.044715f * v * v * v;
    return 0.5f * v * (1.0f + tanhf(0.7978845608028654f * u));
}

__device__ __forceinline__ float ex2f(float x) {
    float r;
    asm("ex2.approx.f32 %0, %1;" : "=f"(r) : "f"(x));
    return r;
}

__device__ __forceinline__ uint32_t smem_u32(const void* p) {
    uint32_t a;
    asm("{ .reg .u64 t; cvta.to.shared.u64 t, %1; cvt.u32.u64 %0, t; }" : "=r"(a) : "l"(p));
    return a;
}

__device__ __forceinline__ unsigned packh2(float lo, float hi) {
    unsigned r;
    asm("cvt.rn.f16x2.f32 %0, %1, %2;" : "=r"(r) : "f"(hi), "f"(lo));
    return r;
}

__device__ __forceinline__ void mma16(float* c, const unsigned* a, const unsigned* b) {
    asm volatile(
        "mma.sync.aligned.m16n8k16.row.col.f32.f16.f16.f32 "
        "{%0,%1,%2,%3}, {%4,%5,%6,%7}, {%8,%9}, {%0,%1,%2,%3};\n"
        : "+f"(c[0]), "+f"(c[1]), "+f"(c[2]), "+f"(c[3])
        : "r"(a[0]), "r"(a[1]), "r"(a[2]), "r"(a[3]),
          "r"(b[0]), "r"(b[1]));
}

__device__ __forceinline__ void ldsm4(unsigned& r0, unsigned& r1, unsigned& r2, unsigned& r3,
                                      uint32_t addr) {
    asm volatile("ldmatrix.sync.aligned.m8n8.x4.shared.b16 {%0,%1,%2,%3}, [%4];"
                 : "=r"(r0), "=r"(r1), "=r"(r2), "=r"(r3) : "r"(addr));
}
__device__ __forceinline__ void ldsm4t(unsigned& r0, unsigned& r1, unsigned& r2, unsigned& r3,
                                       uint32_t addr) {
    asm volatile("ldmatrix.sync.aligned.m8n8.x4.trans.shared.b16 {%0,%1,%2,%3}, [%4];"
                 : "=r"(r0), "=r"(r1), "=r"(r2), "=r"(r3) : "r"(addr));
}

__device__ __forceinline__ void cpa16(uint32_t dst, const void* src) {
    asm volatile("cp.async.cg.shared.global [%0], [%1], 16;" :: "r"(dst), "l"(src));
}
#define CPA_COMMIT() asm volatile("cp.async.commit_group;" ::: "memory")
template<int N> __device__ __forceinline__ void cpa_wait() {
    asm volatile("cp.async.wait_group %0;" :: "n"(N) : "memory");
}

// -------------------- fused f32 -> f16 weight conversion (v2) --------------
// Shift-only addressing, 4 float4 per thread, flat fast path.
// blocks: [0,768)=wq/wk/wv strided, [768,1024)=wo, [1024,2048)=wf1, [2048,3072)=wf2
#define ROUND2_BLOCKS 3072
__global__ void __launch_bounds__(256)
round_all2(const float* __restrict__ wq, const float* __restrict__ wk,
           const float* __restrict__ wv, const float* __restrict__ wo,
           const float* __restrict__ wf1, const float* __restrict__ wf2,
           __half* __restrict__ wqkv, __half* __restrict__ wo16,
           __half* __restrict__ wf116, __half* __restrict__ wf216)
{
    const int blk = blockIdx.x;
    const float* src;
    __half* dst;
    bool strided = false;
    int i;                                   // float4 index within region
    if (blk < 768) {
        int m = blk >> 8;                    // 0,1,2 -> q,k,v
        src = (m == 0) ? wq : (m == 1) ? wk : wv;
        dst = wqkv + m * EMB;
        i = ((blk & 255) << 10) + threadIdx.x * 4;
        strided = true;
    } else if (blk < 1024) {
        src = wo;  dst = wo16;  i = ((blk - 768) << 10) + threadIdx.x * 4;
    } else if (blk < 2048) {
        src = wf1; dst = wf116; i = ((blk - 1024) << 10) + threadIdx.x * 4;
    } else {
        src = wf2; dst = wf216; i = ((blk - 2048) << 10) + threadIdx.x * 4;
    }

    const float4* s4 = (const float4*)src + i;
    float4 v0 = s4[0], v1 = s4[1], v2 = s4[2], v3 = s4[3];
    uint4 o0, o1;
    o0.x = packh2(v0.x, v0.y); o0.y = packh2(v0.z, v0.w);
    o0.z = packh2(v1.x, v1.y); o0.w = packh2(v1.z, v1.w);
    o1.x = packh2(v2.x, v2.y); o1.y = packh2(v2.z, v2.w);
    o1.z = packh2(v3.x, v3.y); o1.w = packh2(v3.z, v3.w);

    __half* d;
    if (strided) {
        int r = i >> 8;                      // 256 f4 per source row (EMB=1024)
        int c = (i & 255) << 2;              // halves within row
        d = dst + (size_t)r * (3 * EMB) + c;
    } else {
        d = dst + (size_t)i * 4;
    }
    *(uint4*)d = o0;
    *(uint4*)(d + 8) = o1;
}

// -------------------- layernorm (fp16 output) -------------------------------
__global__ void __launch_bounds__(256)
ln16_kernel(const float* __restrict__ x, const float* __restrict__ sc,
            const float* __restrict__ sh, __half* __restrict__ out)
{
    __shared__ float red[8];
    __shared__ float stats[2];
    const int row = blockIdx.x, tid = threadIdx.x, lane = tid & 31, warp = tid >> 5;
    const float* xr = x + (size_t)row * EMB;
    float4 v = *(const float4*)(xr + tid * 4);

    float s = v.x + v.y + v.z + v.w;
    #pragma unroll
    for (int o = 16; o > 0; o >>= 1) s += __shfl_xor_sync(0xffffffffu, s, o);
    if (lane == 0) red[warp] = s;
    __syncthreads();
    if (tid == 0) {
        float t = 0.f;
        #pragma unroll
        for (int i = 0; i < 8; i++) t += red[i];
        stats[0] = t * (1.0f / EMB);
    }
    __syncthreads();
    const float mean = stats[0];
    float dx = v.x - mean, dy = v.y - mean, dz = v.z - mean, dw = v.w - mean;
    float ss = dx * dx + dy * dy + dz * dz + dw * dw;
    #pragma unroll
    for (int o = 16; o > 0; o >>= 1) ss += __shfl_xor_sync(0xffffffffu, ss, o);
    if (lane == 0) red[warp] = ss;
    __syncthreads();
    if (tid == 0) {
        float t = 0.f;
        #pragma unroll
        for (int i = 0; i < 8; i++) t += red[i];
        stats[1] = rsqrtf(t * (1.0f / EMB) + 1e-5f);
    }
    __syncthreads();
    const float rstd = stats[1];
    float4 scv = *(const float4*)(sc + tid * 4);
    float4 shv = *(const float4*)(sh + tid * 4);
    __half2 h0 = __floats2half2_rn(scv.x * dx * rstd + shv.x, scv.y * dy * rstd + shv.y);
    __half2 h1 = __floats2half2_rn(scv.z * dz * rstd + shv.z, scv.w * dw * rstd + shv.w);
    __half2* o = (__half2*)(out + (size_t)row * EMB + tid * 4);
    o[0] = h0; o[1] = h1;
}

// -------------------- shared GEMM constants --------------------
#define BK 64
#define A_ROW_B 144
#define B_ROW_B 272

enum { EP_H = 0, EP_GELU_H = 1, EP_RES_F = 2 };

// ==================== GEMM small: 128x128, 128 thr, 2 CTA/SM ===============
#define BM 128
#define BN 128
#define ASTG (BM * A_ROW_B)
#define BSTG (BK * B_ROW_B)
#define STGB (ASTG + BSTG)
#define GEMM_SMEM (3 * STGB)

__device__ __forceinline__ void fill_stage16(uint32_t sA, uint32_t sB,
                                             const __half* __restrict__ A,
                                             const __half* __restrict__ B,
                                             int bm, int bn, int N, int K, int kc, int tid)
{
    #pragma unroll
    for (int i = 0; i < 8; i++) {
        int e = tid + i * 128;
        int row = e >> 3, seg = e & 7;
        cpa16(sA + row * A_ROW_B + seg * 16,
              A + (size_t)(bm + row) * K + kc * BK + seg * 8);
    }
    #pragma unroll
    for (int i = 0; i < 8; i++) {
        int e = tid + i * 128;
        int row = e >> 4, seg = e & 15;
        cpa16(sB + row * B_ROW_B + seg * 16,
              B + (size_t)(kc * BK + row) * N + bn + seg * 8);
    }
}

template<int EPI>
__global__ void __launch_bounds__(128, 2)
gemm16(const __half* __restrict__ A, const __half* __restrict__ B,
       const float* __restrict__ bias, const float* __restrict__ R,
       void* __restrict__ Cv, int M, int N, int K)
{
    extern __shared__ char smem[];
    const uint32_t sbase = smem_u32(smem);

    const int tid = threadIdx.x, lane = tid & 31, warp = tid >> 5;
    const int bm = blockIdx.y * BM, bn = blockIdx.x * BN;
    const int wm = (warp & 1) * 64, wn = (warp >> 1) * 64;
    const int g = lane >> 2, t = lane & 3;
    const int NK = K / BK;

    float c[4][8][4];
    #pragma unroll
    for (int mt = 0; mt < 4; mt++)
        #pragma unroll
        for (int nt = 0; nt < 8; nt++)
            #pragma unroll
            for (int e = 0; e < 4; e++) c[mt][nt][e] = 0.f;

    fill_stage16(sbase,        sbase + ASTG,        A, B, bm, bn, N, K, 0, tid);
    CPA_COMMIT();
    fill_stage16(sbase + STGB, sbase + STGB + ASTG, A, B, bm, bn, N, K, 1, tid);
    CPA_COMMIT();

    const uint32_t laoff = (wm + (lane & 15)) * A_ROW_B + (lane >> 4) * 16;
    const uint32_t lboff = (lane & 15) * B_ROW_B + (lane >> 4) * 16 + wn * 2;

    int stg = 0;
    for (int kt = 0; kt < NK; kt++) {
        if (kt == NK - 1) cpa_wait<0>(); else cpa_wait<1>();
        __syncthreads();

        if (kt + 2 < NK) {
            int fs = kt + 2; fs -= (fs / 3) * 3;
            fill_stage16(sbase + fs * STGB, sbase + fs * STGB + ASTG,
                         A, B, bm, bn, N, K, kt + 2, tid);
            CPA_COMMIT();
        }

        const uint32_t sA = sbase + stg * STGB;
        const uint32_t sB = sA + ASTG;
        const uint32_t la = sA + laoff;
        const uint32_t lb = sB + lboff;

        #pragma unroll
        for (int ks = 0; ks < 4; ks++) {
            unsigned a[4][4], b[8][2];
            #pragma unroll
            for (int mt = 0; mt < 4; mt++)
                ldsm4(a[mt][0], a[mt][1], a[mt][2], a[mt][3],
                      la + mt * (16 * A_ROW_B) + ks * 32);
            #pragma unroll
            for (int np = 0; np < 4; np++) {
                unsigned r0, r1, r2, r3;
                ldsm4t(r0, r1, r2, r3, lb + ks * (16 * B_ROW_B) + np * 32);
                b[2 * np][0] = r0;     b[2 * np][1] = r1;
                b[2 * np + 1][0] = r2; b[2 * np + 1][1] = r3;
            }
            #pragma unroll
            for (int mt = 0; mt < 4; mt++)
                #pragma unroll
                for (int nt = 0; nt < 8; nt++)
                    mma16(c[mt][nt], a[mt], b[nt]);
        }

        stg++; if (stg == 3) stg = 0;
    }

    #pragma unroll
    for (int mt = 0; mt < 4; mt++) {
        #pragma unroll
        for (int nt = 0; nt < 8; nt++) {
            const int row0 = bm + wm + mt * 16 + g;
            const int col  = bn + wn + nt * 8 + t * 2;
            #pragma unroll
            for (int h = 0; h < 2; h++) {
                const int row = row0 + h * 8;
                float v0 = c[mt][nt][2 * h], v1 = c[mt][nt][2 * h + 1];
                const size_t off = (size_t)row * N + col;
                if (EPI == EP_H) {
                    *(__half2*)((__half*)Cv + off) = __floats2half2_rn(v0, v1);
                } else if (EPI == EP_GELU_H) {
                    float2 bb = *(const float2*)(bias + col);
                    *(__half2*)((__half*)Cv + off) =
                        __floats2half2_rn(gelu_f(v0 + bb.x), gelu_f(v1 + bb.y));
                } else {
                    float2 bb = *(const float2*)(bias + col);
                    float2 rr = *(const float2*)(R + off);
                    *(float2*)((float*)Cv + off) =
                        make_float2(v0 + bb.x + rr.x, v1 + bb.y + rr.y);
                }
            }
        }
    }
}

// ==================== GEMM big: 256x128, 256 thr, 1 CTA/SM =================
#define BM2 256
#define ASTG2 (BM2 * A_ROW_B)
#define STGB2 (ASTG2 + BSTG)
#define GEMM2_SMEM (3 * STGB2)

__device__ __forceinline__ void fill_stage16b(uint32_t sA, uint32_t sB,
                                              const __half* __restrict__ A,
                                              const __half* __restrict__ B,
                                              int bm, int bn, int N, int K, int kc, int tid)
{
    #pragma unroll
    for (int i = 0; i < 8; i++) {
        int e = tid + i * 256;
        int row = e >> 3, seg = e & 7;
        cpa16(sA + row * A_ROW_B + seg * 16,
              A + (size_t)(bm + row) * K + kc * BK + seg * 8);
    }
    #pragma unroll
    for (int i = 0; i < 4; i++) {
        int e = tid + i * 256;
        int row = e >> 4, seg = e & 15;
        cpa16(sB + row * B_ROW_B + seg * 16,
              B + (size_t)(kc * BK + row) * N + bn + seg * 8);
    }
}

template<int EPI>
__global__ void __launch_bounds__(256, 1)
gemm16b(const __half* __restrict__ A, const __half* __restrict__ B,
        const float* __restrict__ bias, const float* __restrict__ R,
        void* __restrict__ Cv, int M, int N, int K)
{
    extern __shared__ char smem[];
    const uint32_t sbase = smem_u32(smem);

    const int tid = threadIdx.x, lane = tid & 31, warp = tid >> 5;
    const int bm = blockIdx.y * BM2, bn = blockIdx.x * BN;
    const int wm = (warp & 3) * 64, wn = (warp >> 2) * 64;
    const int g = lane >> 2, t = lane & 3;
    const int NK = K / BK;

    float c[4][8][4];
    #pragma unroll
    for (int mt = 0; mt < 4; mt++)
        #pragma unroll
        for (int nt = 0; nt < 8; nt++)
            #pragma unroll
            for (int e = 0; e < 4; e++) c[mt][nt][e] = 0.f;

    fill_stage16b(sbase,         sbase + ASTG2,         A, B, bm, bn, N, K, 0, tid);
    CPA_COMMIT();
    fill_stage16b(sbase + STGB2, sbase + STGB2 + ASTG2, A, B, bm, bn, N, K, 1, tid);
    CPA_COMMIT();

    const uint32_t laoff = (wm + (lane & 15)) * A_ROW_B + (lane >> 4) * 16;
    const uint32_t lboff = (lane & 15) * B_ROW_B + (lane >> 4) * 16 + wn * 2;

    int stg = 0;
    for (int kt = 0; kt < NK; kt++) {
        if (kt == NK - 1) cpa_wait<0>(); else cpa_wait<1>();
        __syncthreads();

        if (kt + 2 < NK) {
            int fs = kt + 2; fs -= (fs / 3) * 3;
            fill_stage16b(sbase + fs * STGB2, sbase + fs * STGB2 + ASTG2,
                          A, B, bm, bn, N, K, kt + 2, tid);
            CPA_COMMIT();
        }

        const uint32_t sA = sbase + stg * STGB2;
        const uint32_t sB = sA + ASTG2;
        const uint32_t la = sA + laoff;
        const uint32_t lb = sB + lboff;

        #pragma unroll
        for (int ks = 0; ks < 4; ks++) {
            unsigned a[4][4], b[8][2];
            #pragma unroll
            for (int mt = 0; mt < 4; mt++)
                ldsm4(a[mt][0], a[mt][1], a[mt][2], a[mt][3],
                      la + mt * (16 * A_ROW_B) + ks * 32);
            #pragma unroll
            for (int np = 0; np < 4; np++) {
                unsigned r0, r1, r2, r3;
                ldsm4t(r0, r1, r2, r3, lb + ks * (16 * B_ROW_B) + np * 32);
                b[2 * np][0] = r0;     b[2 * np][1] = r1;
                b[2 * np + 1][0] = r2; b[2 * np + 1][1] = r3;
            }
            #pragma unroll
            for (int mt = 0; mt < 4; mt++)
                #pragma unroll
                for (int nt = 0; nt < 8; nt++)
                    mma16(c[mt][nt], a[mt], b[nt]);
        }

        stg++; if (stg == 3) stg = 0;
    }

    #pragma unroll
    for (int mt = 0; mt < 4; mt++) {
        #pragma unroll
        for (int nt = 0; nt < 8; nt++) {
            const int row0 = bm + wm + mt * 16 + g;
            const int col  = bn + wn + nt * 8 + t * 2;
            #pragma unroll
            for (int h = 0; h < 2; h++) {
                const int row = row0 + h * 8;
                float v0 = c[mt][nt][2 * h], v1 = c[mt][nt][2 * h + 1];
                const size_t off = (size_t)row * N + col;
                if (EPI == EP_H) {
                    *(__half2*)((__half*)Cv + off) = __floats2half2_rn(v0, v1);
                } else if (EPI == EP_GELU_H) {
                    float2 bb = *(const float2*)(bias + col);
                    *(__half2*)((__half*)Cv + off) =
                        __floats2half2_rn(gelu_f(v0 + bb.x), gelu_f(v1 + bb.y));
                } else {
                    float2 bb = *(const float2*)(bias + col);
                    float2 rr = *(const float2*)(R + off);
                    *(float2*)((float*)Cv + off) =
                        make_float2(v0 + bb.x + rr.x, v1 + bb.y + rr.y);
                }
            }
        }
    }
}

// -------------------- fp16 causal flash attention (Br=Bc=64, d=64) ---------
// exp2-domain softmax: scale 0.125*log2(e) folded into Q at smem fill.
#define KROW 144
#define KVTILE (64 * KROW)
#define ATT_SMEM (KVTILE + 2 * 2 * KVTILE)

__global__ void __launch_bounds__(128, 2)
attn16(const __half* __restrict__ Qg, const __half* __restrict__ Kg,
       const __half* __restrict__ Vg, __half* __restrict__ O, int ldq)
{
    extern __shared__ char smem[];
    const uint32_t sbase = smem_u32(smem);
    const uint32_t sQ = sbase;

    const int tid = threadIdx.x, lane = tid & 31, warp = tid >> 5;
    const int g = lane >> 2, t = lane & 3;

    const int qt = gridDim.x - 1 - blockIdx.x;   // big tiles first
    const int bh = blockIdx.y;
    const int b = bh >> 4, h = bh & 15;
    const size_t qbase = (size_t)b * SEQ * ldq + (size_t)h * HDIM;
    const size_t obase = (size_t)b * SEQ * EMB + (size_t)h * HDIM;

    auto fill_kv = [&](int s, int j) {
        const uint32_t sK = sbase + KVTILE + s * (2 * KVTILE);
        const uint32_t sV = sK + KVTILE;
        #pragma unroll
        for (int i = 0; i < 4; i++) {
            int e = tid + i * 128;
            int row = e >> 3, seg = e & 7;
            size_t go = qbase + (size_t)(j * 64 + row) * ldq + seg * 8;
            cpa16(sK + row * KROW + seg * 16, Kg + go);
            cpa16(sV + row * KROW + seg * 16, Vg + go);
        }
    };

    fill_kv(0, 0);
    CPA_COMMIT();

    // Q tile -> smem, scaled by 0.125*log2(e) (exp2-domain softmax)
    const __half2 qsc = __half2half2(__float2half(0.18033688f));
    #pragma unroll
    for (int i = 0; i < 4; i++) {
        int e = tid + i * 128;
        int row = e >> 3, seg = e & 7;
        uint4 raw = *(const uint4*)(Qg + qbase + (size_t)(qt * 64 + row) * ldq + seg * 8);
        __half2* hp = (__half2*)&raw;
        hp[0] = __hmul2(hp[0], qsc);
        hp[1] = __hmul2(hp[1], qsc);
        hp[2] = __hmul2(hp[2], qsc);
        hp[3] = __hmul2(hp[3], qsc);
        *(uint4*)(smem + row * KROW + seg * 16) = raw;
    }
    __syncthreads();

    unsigned qa[4][4];
    {
        const uint32_t la = sQ + (warp * 16 + (lane & 15)) * KROW + (lane >> 4) * 16;
        #pragma unroll
        for (int ks = 0; ks < 4; ks++)
            ldsm4(qa[ks][0], qa[ks][1], qa[ks][2], qa[ks][3], la + ks * 32);
    }

    const uint32_t kboff = ((lane & 7) + ((lane >> 4) << 3)) * KROW + ((lane >> 3) & 1) * 16;
    const uint32_t vboff = (lane & 15) * KROW + (lane >> 4) * 16;

    float m0 = -1e30f, m1 = -1e30f, l0 = 0.f, l1 = 0.f;
    float o[8][4];
    #pragma unroll
    for (int dt = 0; dt < 8; dt++)
        #pragma unroll
        for (int e = 0; e < 4; e++) o[dt][e] = 0.f;

    const int r0g = qt * 64 + warp * 16 + g;

    for (int j = 0; j <= qt; j++) {
        if (j < qt) { fill_kv((j + 1) & 1, j + 1); CPA_COMMIT(); }
        if (j < qt) cpa_wait<1>(); else cpa_wait<0>();
        __syncthreads();

        const uint32_t sK = sbase + KVTILE + (j & 1) * (2 * KVTILE);
        const uint32_t sV = sK + KVTILE;

        float s[8][4];
        #pragma unroll
        for (int nt = 0; nt < 8; nt++)
            #pragma unroll
            for (int e = 0; e < 4; e++) s[nt][e] = 0.f;

        #pragma unroll
        for (int ks = 0; ks < 4; ks++) {
            unsigned kb[8][2];
            #pragma unroll
            for (int np = 0; np < 4; np++) {
                unsigned r0, r1, r2, r3;
                ldsm4(r0, r1, r2, r3, sK + kboff + np * (16 * KROW) + ks * 32);
                kb[2 * np][0] = r0;     kb[2 * np][1] = r1;
                kb[2 * np + 1][0] = r2; kb[2 * np + 1][1] = r3;
            }
            #pragma unroll
            for (int nt = 0; nt < 8; nt++)
                mma16(s[nt], qa[ks], kb[nt]);
        }

        // causal mask on diagonal tile (s already in exp2 domain)
        if (j == qt) {
            #pragma unroll
            for (int nt = 0; nt < 8; nt++) {
                int cb = j * 64 + nt * 8 + t * 2;
                if (cb     > r0g)     s[nt][0] = -1e30f;
                if (cb + 1 > r0g)     s[nt][1] = -1e30f;
                if (cb     > r0g + 8) s[nt][2] = -1e30f;
                if (cb + 1 > r0g + 8) s[nt][3] = -1e30f;
            }
        }

        float t0 = -1e30f, t1 = -1e30f;
        #pragma unroll
        for (int nt = 0; nt < 8; nt++) {
            t0 = fmaxf(t0, fmaxf(s[nt][0], s[nt][1]));
            t1 = fmaxf(t1, fmaxf(s[nt][2], s[nt][3]));
        }
        t0 = fmaxf(t0, __shfl_xor_sync(0xffffffffu, t0, 1));
        t0 = fmaxf(t0, __shfl_xor_sync(0xffffffffu, t0, 2));
        t1 = fmaxf(t1, __shfl_xor_sync(0xffffffffu, t1, 1));
        t1 = fmaxf(t1, __shfl_xor_sync(0xffffffffu, t1, 2));
        float mn0 = fmaxf(m0, t0), mn1 = fmaxf(m1, t1);
        float al0 = ex2f(m0 - mn0), al1 = ex2f(m1 - mn1);
        float su0 = 0.f, su1 = 0.f;
        #pragma unroll
        for (int nt = 0; nt < 8; nt++) {
            s[nt][0] = ex2f(s[nt][0] - mn0); su0 += s[nt][0];
            s[nt][1] = ex2f(s[nt][1] - mn0); su0 += s[nt][1];
            s[nt][2] = ex2f(s[nt][2] - mn1); su1 += s[nt][2];
            s[nt][3] = ex2f(s[nt][3] - mn1); su1 += s[nt][3];
        }
        su0 += __shfl_xor_sync(0xffffffffu, su0, 1);
        su0 += __shfl_xor_sync(0xffffffffu, su0, 2);
        su1 += __shfl_xor_sync(0xffffffffu, su1, 1);
        su1 += __shfl_xor_sync(0xffffffffu, su1, 2);
        l0 = l0 * al0 + su0; l1 = l1 * al1 + su1;
        m0 = mn0; m1 = mn1;
        #pragma unroll
        for (int dt = 0; dt < 8; dt++) {
            o[dt][0] *= al0; o[dt][1] *= al0;
            o[dt][2] *= al1; o[dt][3] *= al1;
        }

        #pragma unroll
        for (int ks = 0; ks < 4; ks++) {
            unsigned pa[4];
            pa[0] = packh2(s[2 * ks][0],     s[2 * ks][1]);
            pa[1] = packh2(s[2 * ks][2],     s[2 * ks][3]);
            pa[2] = packh2(s[2 * ks + 1][0], s[2 * ks + 1][1]);
            pa[3] = packh2(s[2 * ks + 1][2], s[2 * ks + 1][3]);
            unsigned vb[8][2];
            #pragma unroll
            for (int np = 0; np < 4; np++) {
                unsigned r0, r1, r2, r3;
                ldsm4t(r0, r1, r2, r3, sV + vboff + ks * (16 * KROW) + np * 32);
                vb[2 * np][0] = r0;     vb[2 * np][1] = r1;
                vb[2 * np + 1][0] = r2; vb[2 * np + 1][1] = r3;
            }
            #pragma unroll
            for (int nt = 0; nt < 8; nt++)
                mma16(o[nt], pa, vb[nt]);
        }

        __syncthreads();
    }

    const float i0 = 1.0f / l0, i1 = 1.0f / l1;
    #pragma unroll
    for (int dt = 0; dt < 8; dt++) {
        int col = dt * 8 + t * 2;
        size_t off0 = obase + (size_t)r0g * EMB + col;
        size_t off1 = obase + (size_t)(r0g + 8) * EMB + col;
        *(__half2*)(O + off0) = __floats2half2_rn(o[dt][0] * i0, o[dt][1] * i0);
        *(__half2*)(O + off1) = __floats2half2_rn(o[dt][2] * i1, o[dt][3] * i1);
    }
}

// -------------------- launch --------------------
extern "C" void kernel_launch(void* const* d_in, const int* in_sizes, int n_in,
                              void* d_out, int out_size)
{
    const float* x     = (const float*)d_in[0];
    const float* w_q   = (const float*)d_in[1];
    const float* w_k   = (const float*)d_in[2];
    const float* w_v   = (const float*)d_in[3];
    const float* w_o   = (const float*)d_in[4];
    const float* b_o   = (const float*)d_in[5];
    const float* ln1s  = (const float*)d_in[6];
    const float* ln1b  = (const float*)d_in[7];
    const float* ln2s  = (const float*)d_in[8];
    const float* ln2b  = (const float*)d_in[9];
    const float* w_ff1 = (const float*)d_in[10];
    const float* b_ff1 = (const float*)d_in[11];
    const float* w_ff2 = (const float*)d_in[12];
    const float* b_ff2 = (const float*)d_in[13];
    float* out = (float*)d_out;

    void *p;
    cudaGetSymbolAddress(&p, g_ln16);   __half* ln16   = (__half*)p;
    cudaGetSymbolAddress(&p, g_qkv16);  __half* qkv16  = (__half*)p;
    cudaGetSymbolAddress(&p, g_ctx16);  __half* ctx16  = (__half*)p;
    cudaGetSymbolAddress(&p, g_ff16);   __half* ff16   = (__half*)p;
    cudaGetSymbolAddress(&p, g_x1);     float*  x1     = (float*)p;
    cudaGetSymbolAddress(&p, g_wqkv16); __half* wqkv16 = (__half*)p;
    cudaGetSymbolAddress(&p, g_wo16);   __half* wo16   = (__half*)p;
    cudaGetSymbolAddress(&p, g_wf116);  __half* wf116  = (__half*)p;
    cudaGetSymbolAddress(&p, g_wf216);  __half* wf216  = (__half*)p;

    cudaFuncSetAttribute((const void*)gemm16<EP_RES_F>,
                         cudaFuncAttributeMaxDynamicSharedMemorySize, GEMM_SMEM);
    cudaFuncSetAttribute((const void*)gemm16b<EP_H>,
                         cudaFuncAttributeMaxDynamicSharedMemorySize, GEMM2_SMEM);
    cudaFuncSetAttribute((const void*)gemm16b<EP_GELU_H>,
                         cudaFuncAttributeMaxDynamicSharedMemorySize, GEMM2_SMEM);
    cudaFuncSetAttribute((const void*)attn16,
                         cudaFuncAttributeMaxDynamicSharedMemorySize, ATT_SMEM);

    // weights -> fp16, single fast launch
    round_all2<<<ROUND2_BLOCKS, 256>>>(w_q, w_k, w_v, w_o, w_ff1, w_ff2,
                                       wqkv16, wo16, wf116, wf216);

    // h = LN1(x)
    ln16_kernel<<<NROWS, 256>>>(x, ln1s, ln1b, ln16);
    // qkv = h @ [Wq|Wk|Wv]
    gemm16b<EP_H><<<dim3(3 * EMB / BN, NROWS / BM2), 256, GEMM2_SMEM>>>(
        ln16, wqkv16, nullptr, nullptr, qkv16, NROWS, 3 * EMB, EMB);
    // ctx = causal attention
    attn16<<<dim3(SEQ / 64, BATCH * NHEADS), 128, ATT_SMEM>>>(
        qkv16, qkv16 + EMB, qkv16 + 2 * EMB, ctx16, 3 * EMB);
    // x1 = x + ctx @ w_o + b_o
    gemm16<EP_RES_F><<<dim3(EMB / BN, NROWS / BM), 128, GEMM_SMEM>>>(
        ctx16, wo16, b_o, x, x1, NROWS, EMB, EMB);
    // h = LN2(x1)
    ln16_kernel<<<NROWS, 256>>>(x1, ln2s, ln2b, ln16);
    // ff = gelu(h @ w_ff1 + b_ff1)
    gemm16b<EP_GELU_H><<<dim3(FFDIM / BN, NROWS / BM2), 256, GEMM2_SMEM>>>(
        ln16, wf116, b_ff1, nullptr, ff16, NROWS, FFDIM, EMB);
    // out = x1 + ff @ w_ff2 + b_ff2
    gemm16<EP_RES_F><<<dim3(EMB / BN, NROWS / BM), 128, GEMM_SMEM>>>(
        ff16, wf216, b_ff2, x1, out, NROWS, EMB, FFDIM);
}

// round 9
// speedup vs baseline: 2.3790x; 1.0045x over previous
#include <cuda_runtime.h>
#include <cuda_fp16.h>
#include <cstdint>
#include <math.h>

#define EMB 1024
#define SEQ 2048
#define BATCH 2
#define NROWS 4096          // BATCH*SEQ
#define FFDIM 4096
#define NHEADS 16
#define HDIM 64

// -------------------- scratch (no allocation allowed) --------------------
__device__ unsigned short g_ln16 [NROWS * EMB];
__device__ unsigned short g_qkv16[(size_t)NROWS * 3 * EMB];
__device__ unsigned short g_ctx16[NROWS * EMB];
__device__ unsigned short g_ff16 [(size_t)NROWS * FFDIM];
__device__ float          g_x1   [NROWS * EMB];
__device__ unsigned short g_wqkv16[(size_t)EMB * 3 * EMB];
__device__ unsigned short g_wo16  [(size_t)EMB * EMB];
__device__ unsigned short g_wf116 [(size_t)EMB * FFDIM];
__device__ unsigned short g_wf216 [(size_t)FFDIM * EMB];

// -------------------- helpers --------------------
__device__ __forceinline__ float gelu_f(float v) {
    float u = v + 0.044715f * v * v * v;
    return 0.5f * v * (1.0f + tanhf(0.7978845608028654f * u));
}

__device__ __forceinline__ float ex2f(float x) {
    float r;
    asm("ex2.approx.f32 %0, %1;" : "=f"(r) : "f"(x));
    return r;
}

__device__ __forceinline__ uint32_t smem_u32(const void* p) {
    uint32_t a;
    asm("{ .reg .u64 t; cvta.to.shared.u64 t, %1; cvt.u32.u64 %0, t; }" : "=r"(a) : "l"(p));
    return a;
}

__device__ __forceinline__ unsigned packh2(float lo, float hi) {
    unsigned r;
    asm("cvt.rn.f16x2.f32 %0, %1, %2;" : "=r"(r) : "f"(hi), "f"(lo));
    return r;
}

__device__ __forceinline__ void mma16(float* c, const unsigned* a, const unsigned* b) {
    asm volatile(
        "mma.sync.aligned.m16n8k16.row.col.f32.f16.f16.f32 "
        "{%0,%1,%2,%3}, {%4,%5,%6,%7}, {%8,%9}, {%0,%1,%2,%3};\n"
        : "+f"(c[0]), "+f"(c[1]), "+f"(c[2]), "+f"(c[3])
        : "r"(a[0]), "r"(a[1]), "r"(a[2]), "r"(a[3]),
          "r"(b[0]), "r"(b[1]));
}

__device__ __forceinline__ void ldsm4(unsigned& r0, unsigned& r1, unsigned& r2, unsigned& r3,
                                      uint32_t addr) {
    asm volatile("ldmatrix.sync.aligned.m8n8.x4.shared.b16 {%0,%1,%2,%3}, [%4];"
                 : "=r"(r0), "=r"(r1), "=r"(r2), "=r"(r3) : "r"(addr));
}
__device__ __forceinline__ void ldsm4t(unsigned& r0, unsigned& r1, unsigned& r2, unsigned& r3,
                                       uint32_t addr) {
    asm volatile("ldmatrix.sync.aligned.m8n8.x4.trans.shared.b16 {%0,%1,%2,%3}, [%4];"
                 : "=r"(r0), "=r"(r1), "=r"(r2), "=r"(r3) : "r"(addr));
}

__device__ __forceinline__ void cpa16(uint32_t dst, const void* src) {
    asm volatile("cp.async.cg.shared.global [%0], [%1], 16;" :: "r"(dst), "l"(src));
}
#define CPA_COMMIT() asm volatile("cp.async.commit_group;" ::: "memory")
template<int N> __device__ __forceinline__ void cpa_wait() {
    asm volatile("cp.async.wait_group %0;" :: "n"(N) : "memory");
}

// -------------------- fused f32 -> f16 weight conversion (v2) --------------
#define ROUND2_BLOCKS 3072
__global__ void __launch_bounds__(256)
round_all2(const float* __restrict__ wq, const float* __restrict__ wk,
           const float* __restrict__ wv, const float* __restrict__ wo,
           const float* __restrict__ wf1, const float* __restrict__ wf2,
           __half* __restrict__ wqkv, __half* __restrict__ wo16,
           __half* __restrict__ wf116, __half* __restrict__ wf216)
{
    const int blk = blockIdx.x;
    const float* src;
    __half* dst;
    bool strided = false;
    int i;
    if (blk < 768) {
        int m = blk >> 8;
        src = (m == 0) ? wq : (m == 1) ? wk : wv;
        dst = wqkv + m * EMB;
        i = ((blk & 255) << 10) + threadIdx.x * 4;
        strided = true;
    } else if (blk < 1024) {
        src = wo;  dst = wo16;  i = ((blk - 768) << 10) + threadIdx.x * 4;
    } else if (blk < 2048) {
        src = wf1; dst = wf116; i = ((blk - 1024) << 10) + threadIdx.x * 4;
    } else {
        src = wf2; dst = wf216; i = ((blk - 2048) << 10) + threadIdx.x * 4;
    }

    const float4* s4 = (const float4*)src + i;
    float4 v0 = s4[0], v1 = s4[1], v2 = s4[2], v3 = s4[3];
    uint4 o0, o1;
    o0.x = packh2(v0.x, v0.y); o0.y = packh2(v0.z, v0.w);
    o0.z = packh2(v1.x, v1.y); o0.w = packh2(v1.z, v1.w);
    o1.x = packh2(v2.x, v2.y); o1.y = packh2(v2.z, v2.w);
    o1.z = packh2(v3.x, v3.y); o1.w = packh2(v3.z, v3.w);

    __half* d;
    if (strided) {
        int r = i >> 8;
        int c = (i & 255) << 2;
        d = dst + (size_t)r * (3 * EMB) + c;
    } else {
        d = dst + (size_t)i * 4;
    }
    *(uint4*)d = o0;
    *(uint4*)(d + 8) = o1;
}

// -------------------- layernorm (fp16 output) -------------------------------
__global__ void __launch_bounds__(256)
ln16_kernel(const float* __restrict__ x, const float* __restrict__ sc,
            const float* __restrict__ sh, __half* __restrict__ out)
{
    __shared__ float red[8];
    __shared__ float stats[2];
    const int row = blockIdx.x, tid = threadIdx.x, lane = tid & 31, warp = tid >> 5;
    const float* xr = x + (size_t)row * EMB;
    float4 v = *(const float4*)(xr + tid * 4);

    float s = v.x + v.y + v.z + v.w;
    #pragma unroll
    for (int o = 16; o > 0; o >>= 1) s += __shfl_xor_sync(0xffffffffu, s, o);
    if (lane == 0) red[warp] = s;
    __syncthreads();
    if (tid == 0) {
        float t = 0.f;
        #pragma unroll
        for (int i = 0; i < 8; i++) t += red[i];
        stats[0] = t * (1.0f / EMB);
    }
    __syncthreads();
    const float mean = stats[0];
    float dx = v.x - mean, dy = v.y - mean, dz = v.z - mean, dw = v.w - mean;
    float ss = dx * dx + dy * dy + dz * dz + dw * dw;
    #pragma unroll
    for (int o = 16; o > 0; o >>= 1) ss += __shfl_xor_sync(0xffffffffu, ss, o);
    if (lane == 0) red[warp] = ss;
    __syncthreads();
    if (tid == 0) {
        float t = 0.f;
        #pragma unroll
        for (int i = 0; i < 8; i++) t += red[i];
        stats[1] = rsqrtf(t * (1.0f / EMB) + 1e-5f);
    }
    __syncthreads();
    const float rstd = stats[1];
    float4 scv = *(const float4*)(sc + tid * 4);
    float4 shv = *(const float4*)(sh + tid * 4);
    __half2 h0 = __floats2half2_rn(scv.x * dx * rstd + shv.x, scv.y * dy * rstd + shv.y);
    __half2 h1 = __floats2half2_rn(scv.z * dz * rstd + shv.z, scv.w * dw * rstd + shv.w);
    __half2* o = (__half2*)(out + (size_t)row * EMB + tid * 4);
    o[0] = h0; o[1] = h1;
}

// -------------------- shared GEMM constants --------------------
#define BK 64
#define A_ROW_B 144
#define B_ROW_B 272

enum { EP_H = 0, EP_GELU_H = 1, EP_RES_F = 2 };

// ==================== GEMM small: 128x128, 128 thr, 2 CTA/SM ===============
#define BM 128
#define BN 128
#define ASTG (BM * A_ROW_B)
#define BSTG (BK * B_ROW_B)
#define STGB (ASTG + BSTG)
#define GEMM_SMEM (3 * STGB)

__device__ __forceinline__ void fill_stage16(uint32_t sA, uint32_t sB,
                                             const __half* __restrict__ A,
                                             const __half* __restrict__ B,
                                             int bm, int bn, int N, int K, int kc, int tid)
{
    #pragma unroll
    for (int i = 0; i < 8; i++) {
        int e = tid + i * 128;
        int row = e >> 3, seg = e & 7;
        cpa16(sA + row * A_ROW_B + seg * 16,
              A + (size_t)(bm + row) * K + kc * BK + seg * 8);
    }
    #pragma unroll
    for (int i = 0; i < 8; i++) {
        int e = tid + i * 128;
        int row = e >> 4, seg = e & 15;
        cpa16(sB + row * B_ROW_B + seg * 16,
              B + (size_t)(kc * BK + row) * N + bn + seg * 8);
    }
}

template<int EPI>
__global__ void __launch_bounds__(128, 2)
gemm16(const __half* __restrict__ A, const __half* __restrict__ B,
       const float* __restrict__ bias, const float* __restrict__ R,
       void* __restrict__ Cv, int M, int N, int K)
{
    extern __shared__ char smem[];
    const uint32_t sbase = smem_u32(smem);

    const int tid = threadIdx.x, lane = tid & 31, warp = tid >> 5;
    const int bm = blockIdx.y * BM, bn = blockIdx.x * BN;
    const int wm = (warp & 1) * 64, wn = (warp >> 1) * 64;
    const int g = lane >> 2, t = lane & 3;
    const int NK = K / BK;

    float c[4][8][4];
    #pragma unroll
    for (int mt = 0; mt < 4; mt++)
        #pragma unroll
        for (int nt = 0; nt < 8; nt++)
            #pragma unroll
            for (int e = 0; e < 4; e++) c[mt][nt][e] = 0.f;

    fill_stage16(sbase,        sbase + ASTG,        A, B, bm, bn, N, K, 0, tid);
    CPA_COMMIT();
    fill_stage16(sbase + STGB, sbase + STGB + ASTG, A, B, bm, bn, N, K, 1, tid);
    CPA_COMMIT();

    const uint32_t laoff = (wm + (lane & 15)) * A_ROW_B + (lane >> 4) * 16;
    const uint32_t lboff = (lane & 15) * B_ROW_B + (lane >> 4) * 16 + wn * 2;

    int stg = 0;
    for (int kt = 0; kt < NK; kt++) {
        if (kt == NK - 1) cpa_wait<0>(); else cpa_wait<1>();
        __syncthreads();

        if (kt + 2 < NK) {
            int fs = kt + 2; fs -= (fs / 3) * 3;
            fill_stage16(sbase + fs * STGB, sbase + fs * STGB + ASTG,
                         A, B, bm, bn, N, K, kt + 2, tid);
            CPA_COMMIT();
        }

        const uint32_t sA = sbase + stg * STGB;
        const uint32_t sB = sA + ASTG;
        const uint32_t la = sA + laoff;
        const uint32_t lb = sB + lboff;

        #pragma unroll
        for (int ks = 0; ks < 4; ks++) {
            unsigned a[4][4], b[8][2];
            #pragma unroll
            for (int mt = 0; mt < 4; mt++)
                ldsm4(a[mt][0], a[mt][1], a[mt][2], a[mt][3],
                      la + mt * (16 * A_ROW_B) + ks * 32);
            #pragma unroll
            for (int np = 0; np < 4; np++) {
                unsigned r0, r1, r2, r3;
                ldsm4t(r0, r1, r2, r3, lb + ks * (16 * B_ROW_B) + np * 32);
                b[2 * np][0] = r0;     b[2 * np][1] = r1;
                b[2 * np + 1][0] = r2; b[2 * np + 1][1] = r3;
            }
            #pragma unroll
            for (int mt = 0; mt < 4; mt++)
                #pragma unroll
                for (int nt = 0; nt < 8; nt++)
                    mma16(c[mt][nt], a[mt], b[nt]);
        }

        stg++; if (stg == 3) stg = 0;
    }

    #pragma unroll
    for (int mt = 0; mt < 4; mt++) {
        #pragma unroll
        for (int nt = 0; nt < 8; nt++) {
            const int row0 = bm + wm + mt * 16 + g;
            const int col  = bn + wn + nt * 8 + t * 2;
            #pragma unroll
            for (int h = 0; h < 2; h++) {
                const int row = row0 + h * 8;
                float v0 = c[mt][nt][2 * h], v1 = c[mt][nt][2 * h + 1];
                const size_t off = (size_t)row * N + col;
                if (EPI == EP_H) {
                    *(__half2*)((__half*)Cv + off) = __floats2half2_rn(v0, v1);
                } else if (EPI == EP_GELU_H) {
                    float2 bb = *(const float2*)(bias + col);
                    *(__half2*)((__half*)Cv + off) =
                        __floats2half2_rn(gelu_f(v0 + bb.x), gelu_f(v1 + bb.y));
                } else {
                    float2 bb = *(const float2*)(bias + col);
                    float2 rr = *(const float2*)(R + off);
                    *(float2*)((float*)Cv + off) =
                        make_float2(v0 + bb.x + rr.x, v1 + bb.y + rr.y);
                }
            }
        }
    }
}

// ==================== GEMM big: 256x128, 256 thr, 1 CTA/SM =================
#define BM2 256
#define ASTG2 (BM2 * A_ROW_B)
#define STGB2 (ASTG2 + BSTG)
#define GEMM2_SMEM (3 * STGB2)

__device__ __forceinline__ void fill_stage16b(uint32_t sA, uint32_t sB,
                                              const __half* __restrict__ A,
                                              const __half* __restrict__ B,
                                              int bm, int bn, int N, int K, int kc, int tid)
{
    #pragma unroll
    for (int i = 0; i < 8; i++) {
        int e = tid + i * 256;
        int row = e >> 3, seg = e & 7;
        cpa16(sA + row * A_ROW_B + seg * 16,
              A + (size_t)(bm + row) * K + kc * BK + seg * 8);
    }
    #pragma unroll
    for (int i = 0; i < 4; i++) {
        int e = tid + i * 256;
        int row = e >> 4, seg = e & 15;
        cpa16(sB + row * B_ROW_B + seg * 16,
              B + (size_t)(kc * BK + row) * N + bn + seg * 8);
    }
}

template<int EPI>
__global__ void __launch_bounds__(256, 1)
gemm16b(const __half* __restrict__ A, const __half* __restrict__ B,
        const float* __restrict__ bias, const float* __restrict__ R,
        void* __restrict__ Cv, int M, int N, int K)
{
    extern __shared__ char smem[];
    const uint32_t sbase = smem_u32(smem);

    const int tid = threadIdx.x, lane = tid & 31, warp = tid >> 5;
    const int bm = blockIdx.y * BM2, bn = blockIdx.x * BN;
    const int wm = (warp & 3) * 64, wn = (warp >> 2) * 64;
    const int g = lane >> 2, t = lane & 3;
    const int NK = K / BK;

    float c[4][8][4];
    #pragma unroll
    for (int mt = 0; mt < 4; mt++)
        #pragma unroll
        for (int nt = 0; nt < 8; nt++)
            #pragma unroll
            for (int e = 0; e < 4; e++) c[mt][nt][e] = 0.f;

    fill_stage16b(sbase,         sbase + ASTG2,         A, B, bm, bn, N, K, 0, tid);
    CPA_COMMIT();
    fill_stage16b(sbase + STGB2, sbase + STGB2 + ASTG2, A, B, bm, bn, N, K, 1, tid);
    CPA_COMMIT();

    const uint32_t laoff = (wm + (lane & 15)) * A_ROW_B + (lane >> 4) * 16;
    const uint32_t lboff = (lane & 15) * B_ROW_B + (lane >> 4) * 16 + wn * 2;

    int stg = 0;
    for (int kt = 0; kt < NK; kt++) {
        if (kt == NK - 1) cpa_wait<0>(); else cpa_wait<1>();
        __syncthreads();

        if (kt + 2 < NK) {
            int fs = kt + 2; fs -= (fs / 3) * 3;
            fill_stage16b(sbase + fs * STGB2, sbase + fs * STGB2 + ASTG2,
                          A, B, bm, bn, N, K, kt + 2, tid);
            CPA_COMMIT();
        }

        const uint32_t sA = sbase + stg * STGB2;
        const uint32_t sB = sA + ASTG2;
        const uint32_t la = sA + laoff;
        const uint32_t lb = sB + lboff;

        #pragma unroll
        for (int ks = 0; ks < 4; ks++) {
            unsigned a[4][4], b[8][2];
            #pragma unroll
            for (int mt = 0; mt < 4; mt++)
                ldsm4(a[mt][0], a[mt][1], a[mt][2], a[mt][3],
                      la + mt * (16 * A_ROW_B) + ks * 32);
            #pragma unroll
            for (int np = 0; np < 4; np++) {
                unsigned r0, r1, r2, r3;
                ldsm4t(r0, r1, r2, r3, lb + ks * (16 * B_ROW_B) + np * 32);
                b[2 * np][0] = r0;     b[2 * np][1] = r1;
                b[2 * np + 1][0] = r2; b[2 * np + 1][1] = r3;
            }
            #pragma unroll
            for (int mt = 0; mt < 4; mt++)
                #pragma unroll
                for (int nt = 0; nt < 8; nt++)
                    mma16(c[mt][nt], a[mt], b[nt]);
        }

        stg++; if (stg == 3) stg = 0;
    }

    #pragma unroll
    for (int mt = 0; mt < 4; mt++) {
        #pragma unroll
        for (int nt = 0; nt < 8; nt++) {
            const int row0 = bm + wm + mt * 16 + g;
            const int col  = bn + wn + nt * 8 + t * 2;
            #pragma unroll
            for (int h = 0; h < 2; h++) {
                const int row = row0 + h * 8;
                float v0 = c[mt][nt][2 * h], v1 = c[mt][nt][2 * h + 1];
                const size_t off = (size_t)row * N + col;
                if (EPI == EP_H) {
                    *(__half2*)((__half*)Cv + off) = __floats2half2_rn(v0, v1);
                } else if (EPI == EP_GELU_H) {
                    float2 bb = *(const float2*)(bias + col);
                    *(__half2*)((__half*)Cv + off) =
                        __floats2half2_rn(gelu_f(v0 + bb.x), gelu_f(v1 + bb.y));
                } else {
                    float2 bb = *(const float2*)(bias + col);
                    float2 rr = *(const float2*)(R + off);
                    *(float2*)((float*)Cv + off) =
                        make_float2(v0 + bb.x + rr.x, v1 + bb.y + rr.y);
                }
            }
        }
    }
}

// -------------------- fp16 causal flash attention (Br=Bc=64, d=64) ---------
// exp2-domain softmax, scale folded into Q. 3 CTAs/SM for latency hiding.
#define KROW 144
#define KVTILE (64 * KROW)
#define ATT_SMEM (KVTILE + 2 * 2 * KVTILE)

__global__ void __launch_bounds__(128, 3)
attn16(const __half* __restrict__ Qg, const __half* __restrict__ Kg,
       const __half* __restrict__ Vg, __half* __restrict__ O, int ldq)
{
    extern __shared__ char smem[];
    const uint32_t sbase = smem_u32(smem);
    const uint32_t sQ = sbase;

    const int tid = threadIdx.x, lane = tid & 31, warp = tid >> 5;
    const int g = lane >> 2, t = lane & 3;

    const int qt = gridDim.x - 1 - blockIdx.x;   // big tiles first
    const int bh = blockIdx.y;
    const int b = bh >> 4, h = bh & 15;
    const size_t qbase = (size_t)b * SEQ * ldq + (size_t)h * HDIM;
    const size_t obase = (size_t)b * SEQ * EMB + (size_t)h * HDIM;

    auto fill_kv = [&](int s, int j) {
        const uint32_t sK = sbase + KVTILE + s * (2 * KVTILE);
        const uint32_t sV = sK + KVTILE;
        #pragma unroll
        for (int i = 0; i < 4; i++) {
            int e = tid + i * 128;
            int row = e >> 3, seg = e & 7;
            size_t go = qbase + (size_t)(j * 64 + row) * ldq + seg * 8;
            cpa16(sK + row * KROW + seg * 16, Kg + go);
            cpa16(sV + row * KROW + seg * 16, Vg + go);
        }
    };

    fill_kv(0, 0);
    CPA_COMMIT();

    // Q tile -> smem, scaled by 0.125*log2(e) (exp2-domain softmax)
    const __half2 qsc = __half2half2(__float2half(0.18033688f));
    #pragma unroll
    for (int i = 0; i < 4; i++) {
        int e = tid + i * 128;
        int row = e >> 3, seg = e & 7;
        uint4 raw = *(const uint4*)(Qg + qbase + (size_t)(qt * 64 + row) * ldq + seg * 8);
        __half2* hp = (__half2*)&raw;
        hp[0] = __hmul2(hp[0], qsc);
        hp[1] = __hmul2(hp[1], qsc);
        hp[2] = __hmul2(hp[2], qsc);
        hp[3] = __hmul2(hp[3], qsc);
        *(uint4*)(smem + row * KROW + seg * 16) = raw;
    }
    __syncthreads();

    unsigned qa[4][4];
    {
        const uint32_t la = sQ + (warp * 16 + (lane & 15)) * KROW + (lane >> 4) * 16;
        #pragma unroll
        for (int ks = 0; ks < 4; ks++)
            ldsm4(qa[ks][0], qa[ks][1], qa[ks][2], qa[ks][3], la + ks * 32);
    }

    const uint32_t kboff = ((lane & 7) + ((lane >> 4) << 3)) * KROW + ((lane >> 3) & 1) * 16;
    const uint32_t vboff = (lane & 15) * KROW + (lane >> 4) * 16;

    float m0 = -1e30f, m1 = -1e30f, l0 = 0.f, l1 = 0.f;
    float o[8][4];
    #pragma unroll
    for (int dt = 0; dt < 8; dt++)
        #pragma unroll
        for (int e = 0; e < 4; e++) o[dt][e] = 0.f;

    const int r0g = qt * 64 + warp * 16 + g;

    for (int j = 0; j <= qt; j++) {
        if (j < qt) { fill_kv((j + 1) & 1, j + 1); CPA_COMMIT(); }
        if (j < qt) cpa_wait<1>(); else cpa_wait<0>();
        __syncthreads();

        const uint32_t sK = sbase + KVTILE + (j & 1) * (2 * KVTILE);
        const uint32_t sV = sK + KVTILE;

        float s[8][4];
        #pragma unroll
        for (int nt = 0; nt < 8; nt++)
            #pragma unroll
            for (int e = 0; e < 4; e++) s[nt][e] = 0.f;

        #pragma unroll
        for (int ks = 0; ks < 4; ks++) {
            unsigned kb[8][2];
            #pragma unroll
            for (int np = 0; np < 4; np++) {
                unsigned r0, r1, r2, r3;
                ldsm4(r0, r1, r2, r3, sK + kboff + np * (16 * KROW) + ks * 32);
                kb[2 * np][0] = r0;     kb[2 * np][1] = r1;
                kb[2 * np + 1][0] = r2; kb[2 * np + 1][1] = r3;
            }
            #pragma unroll
            for (int nt = 0; nt < 8; nt++)
                mma16(s[nt], qa[ks], kb[nt]);
        }

        // causal mask on diagonal tile (s already in exp2 domain)
        if (j == qt) {
            #pragma unroll
            for (int nt = 0; nt < 8; nt++) {
                int cb = j * 64 + nt * 8 + t * 2;
                if (cb     > r0g)     s[nt][0] = -1e30f;
                if (cb + 1 > r0g)     s[nt][1] = -1e30f;
                if (cb     > r0g + 8) s[nt][2] = -1e30f;
                if (cb + 1 > r0g + 8) s[nt][3] = -1e30f;
            }
        }

        float t0 = -1e30f, t1 = -1e30f;
        #pragma unroll
        for (int nt = 0; nt < 8; nt++) {
            t0 = fmaxf(t0, fmaxf(s[nt][0], s[nt][1]));
            t1 = fmaxf(t1, fmaxf(s[nt][2], s[nt][3]));
        }
        t0 = fmaxf(t0, __shfl_xor_sync(0xffffffffu, t0, 1));
        t0 = fmaxf(t0, __shfl_xor_sync(0xffffffffu, t0, 2));
        t1 = fmaxf(t1, __shfl_xor_sync(0xffffffffu, t1, 1));
        t1 = fmaxf(t1, __shfl_xor_sync(0xffffffffu, t1, 2));
        float mn0 = fmaxf(m0, t0), mn1 = fmaxf(m1, t1);
        float al0 = ex2f(m0 - mn0), al1 = ex2f(m1 - mn1);
        float su0 = 0.f, su1 = 0.f;
        #pragma unroll
        for (int nt = 0; nt < 8; nt++) {
            s[nt][0] = ex2f(s[nt][0] - mn0); su0 += s[nt][0];
            s[nt][1] = ex2f(s[nt][1] - mn0); su0 += s[nt][1];
            s[nt][2] = ex2f(s[nt][2] - mn1); su1 += s[nt][2];
            s[nt][3] = ex2f(s[nt][3] - mn1); su1 += s[nt][3];
        }
        su0 += __shfl_xor_sync(0xffffffffu, su0, 1);
        su0 += __shfl_xor_sync(0xffffffffu, su0, 2);
        su1 += __shfl_xor_sync(0xffffffffu, su1, 1);
        su1 += __shfl_xor_sync(0xffffffffu, su1, 2);
        l0 = l0 * al0 + su0; l1 = l1 * al1 + su1;
        m0 = mn0; m1 = mn1;
        #pragma unroll
        for (int dt = 0; dt < 8; dt++) {
            o[dt][0] *= al0; o[dt][1] *= al0;
            o[dt][2] *= al1; o[dt][3] *= al1;
        }

        #pragma unroll
        for (int ks = 0; ks < 4; ks++) {
            unsigned pa[4];
            pa[0] = packh2(s[2 * ks][0],     s[2 * ks][1]);
            pa[1] = packh2(s[2 * ks][2],     s[2 * ks][3]);
            pa[2] = packh2(s[2 * ks + 1][0], s[2 * ks + 1][1]);
            pa[3] = packh2(s[2 * ks + 1][2], s[2 * ks + 1][3]);
            unsigned vb[8][2];
            #pragma unroll
            for (int np = 0; np < 4; np++) {
                unsigned r0, r1, r2, r3;
                ldsm4t(r0, r1, r2, r3, sV + vboff + ks * (16 * KROW) + np * 32);
                vb[2 * np][0] = r0;     vb[2 * np][1] = r1;
                vb[2 * np + 1][0] = r2; vb[2 * np + 1][1] = r3;
            }
            #pragma unroll
            for (int nt = 0; nt < 8; nt++)
                mma16(o[nt], pa, vb[nt]);
        }

        __syncthreads();
    }

    const float i0 = 1.0f / l0, i1 = 1.0f / l1;
    #pragma unroll
    for (int dt = 0; dt < 8; dt++) {
        int col = dt * 8 + t * 2;
        size_t off0 = obase + (size_t)r0g * EMB + col;
        size_t off1 = obase + (size_t)(r0g + 8) * EMB + col;
        *(__half2*)(O + off0) = __floats2half2_rn(o[dt][0] * i0, o[dt][1] * i0);
        *(__half2*)(O + off1) = __floats2half2_rn(o[dt][2] * i1, o[dt][3] * i1);
    }
}

// -------------------- launch --------------------
extern "C" void kernel_launch(void* const* d_in, const int* in_sizes, int n_in,
                              void* d_out, int out_size)
{
    const float* x     = (const float*)d_in[0];
    const float* w_q   = (const float*)d_in[1];
    const float* w_k   = (const float*)d_in[2];
    const float* w_v   = (const float*)d_in[3];
    const float* w_o   = (const float*)d_in[4];
    const float* b_o   = (const float*)d_in[5];
    const float* ln1s  = (const float*)d_in[6];
    const float* ln1b  = (const float*)d_in[7];
    const float* ln2s  = (const float*)d_in[8];
    const float* ln2b  = (const float*)d_in[9];
    const float* w_ff1 = (const float*)d_in[10];
    const float* b_ff1 = (const float*)d_in[11];
    const float* w_ff2 = (const float*)d_in[12];
    const float* b_ff2 = (const float*)d_in[13];
    float* out = (float*)d_out;

    void *p;
    cudaGetSymbolAddress(&p, g_ln16);   __half* ln16   = (__half*)p;
    cudaGetSymbolAddress(&p, g_qkv16);  __half* qkv16  = (__half*)p;
    cudaGetSymbolAddress(&p, g_ctx16);  __half* ctx16  = (__half*)p;
    cudaGetSymbolAddress(&p, g_ff16);   __half* ff16   = (__half*)p;
    cudaGetSymbolAddress(&p, g_x1);     float*  x1     = (float*)p;
    cudaGetSymbolAddress(&p, g_wqkv16); __half* wqkv16 = (__half*)p;
    cudaGetSymbolAddress(&p, g_wo16);   __half* wo16   = (__half*)p;
    cudaGetSymbolAddress(&p, g_wf116);  __half* wf116  = (__half*)p;
    cudaGetSymbolAddress(&p, g_wf216);  __half* wf216  = (__half*)p;

    cudaFuncSetAttribute((const void*)gemm16<EP_RES_F>,
                         cudaFuncAttributeMaxDynamicSharedMemorySize, GEMM_SMEM);
    cudaFuncSetAttribute((const void*)gemm16b<EP_H>,
                         cudaFuncAttributeMaxDynamicSharedMemorySize, GEMM2_SMEM);
    cudaFuncSetAttribute((const void*)gemm16b<EP_GELU_H>,
                         cudaFuncAttributeMaxDynamicSharedMemorySize, GEMM2_SMEM);
    cudaFuncSetAttribute((const void*)attn16,
                         cudaFuncAttributeMaxDynamicSharedMemorySize, ATT_SMEM);

    // weights -> fp16, single fast launch
    round_all2<<<ROUND2_BLOCKS, 256>>>(w_q, w_k, w_v, w_o, w_ff1, w_ff2,
                                       wqkv16, wo16, wf116, wf216);

    // h = LN1(x)
    ln16_kernel<<<NROWS, 256>>>(x, ln1s, ln1b, ln16);
    // qkv = h @ [Wq|Wk|Wv]
    gemm16b<EP_H><<<dim3(3 * EMB / BN, NROWS / BM2), 256, GEMM2_SMEM>>>(
        ln16, wqkv16, nullptr, nullptr, qkv16, NROWS, 3 * EMB, EMB);
    // ctx = causal attention
    attn16<<<dim3(SEQ / 64, BATCH * NHEADS), 128, ATT_SMEM>>>(
        qkv16, qkv16 + EMB, qkv16 + 2 * EMB, ctx16, 3 * EMB);
    // x1 = x + ctx @ w_o + b_o
    gemm16<EP_RES_F><<<dim3(EMB / BN, NROWS / BM), 128, GEMM_SMEM>>>(
        ctx16, wo16, b_o, x, x1, NROWS, EMB, EMB);
    // h = LN2(x1)
    ln16_kernel<<<NROWS, 256>>>(x1, ln2s, ln2b, ln16);
    // ff = gelu(h @ w_ff1 + b_ff1)
    gemm16b<EP_GELU_H><<<dim3(FFDIM / BN, NROWS / BM2), 256, GEMM2_SMEM>>>(
        ln16, wf116, b_ff1, nullptr, ff16, NROWS, FFDIM, EMB);
    // out = x1 + ff @ w_ff2 + b_ff2
    gemm16<EP_RES_F><<<dim3(EMB / BN, NROWS / BM), 128, GEMM_SMEM>>>(
        ff16, wf216, b_ff2, x1, out, NROWS, EMB, FFDIM);
}